// round 2
// baseline (speedup 1.0000x reference)
#include <cuda_runtime.h>
#include <cstdint>

// ============================================================================
// Problem: x[4, 4096, 2048]; Wi/Wf/Wg/Wo [2048, 2048]; w_norm [2048]; fp32.
// Pipeline: GEMM(i|f|g) -> chunked linear scan -> gated RMS stats -> GEMM(out)
// Tensor path: legacy mma.sync.m16n8k8 tf32 (compute_103-compatible; tcgen05
// PTX is rejected because the harness compiles via virtual arch compute_103).
// ============================================================================
constexpr int BB = 4;
constexpr int SS = 4096;
constexpr int DD = 2048;
constexpr int RM = BB * SS;                 // 16384 rows
constexpr size_t PLANE = (size_t)RM * DD;   // 33,554,432 elements

constexpr int TC  = 256;                    // scan chunk length
constexpr int NCH = SS / TC;                // 16 chunks

// ---------------------------------------------------------------------------
// Device scratch (static; allocations are forbidden)
// ---------------------------------------------------------------------------
__device__ float g_proj[3 * PLANE];         // i, f, g planes
__device__ float g_xg[PLANE];               // xg * w_norm
__device__ float g_carryA[BB * NCH * DD];
__device__ float g_carryB[BB * NCH * DD];
__device__ float g_h0[BB * NCH * DD];
__device__ float g_part[(size_t)RM * 64];   // per-row per-warp sumsq partials
__device__ float g_sumsq[RM];

// ---------------------------------------------------------------------------
// PTX helpers (sm_80-era only: cp.async + mma.sync — safe under compute_103)
// ---------------------------------------------------------------------------
__device__ __forceinline__ uint32_t smem_u32(const void* p) {
    uint32_t a;
    asm("{ .reg .u64 t; cvta.to.shared.u64 t, %1; cvt.u32.u64 %0, t; }"
        : "=r"(a) : "l"(p));
    return a;
}

#define CP_ASYNC16(dst, src) \
    asm volatile("cp.async.cg.shared.global [%0], [%1], 16;" \
                 :: "r"(dst), "l"(src))
#define CP_COMMIT() asm volatile("cp.async.commit_group;" ::: "memory")
#define CP_WAIT(n)  asm volatile("cp.async.wait_group %0;" :: "n"(n) : "memory")

__device__ __forceinline__ uint32_t cvt_tf32(float f) {
    uint32_t u;
    asm("cvt.rna.tf32.f32 %0, %1;" : "=r"(u) : "f"(f));
    return u;
}

// D = A(16x8 row) * B(8x8 col) + D, tf32 inputs, fp32 accum.
__device__ __forceinline__ void mma8(float* c, const uint32_t* a, const uint32_t* b) {
    asm volatile(
        "mma.sync.aligned.m16n8k8.row.col.f32.tf32.tf32.f32 "
        "{%0,%1,%2,%3}, {%4,%5,%6,%7}, {%8,%9}, {%0,%1,%2,%3};"
        : "+f"(c[0]), "+f"(c[1]), "+f"(c[2]), "+f"(c[3])
        : "r"(a[0]), "r"(a[1]), "r"(a[2]), "r"(a[3]), "r"(b[0]), "r"(b[1]));
}

// ---------------------------------------------------------------------------
// tf32 GEMM: C[m,n] = sum_k A[m,k]*B[n,k], A,B row-major.
// CTA tile 128x256x32, 256 threads, 8 warps of 64x64, 4-stage cp.async.
// MODE 0: A=x, B={Wi|Wf|Wg by n block}; writes raw i/f/g planes.
// MODE 1: A=g_xg, B=Wo; epilogue scales each row by rsqrt(mean sumsq + eps).
// ---------------------------------------------------------------------------
constexpr int MT = 128, NT = 256, KT = 32;
constexpr int NSLAB  = DD / KT;             // 64
constexpr int STAGES = 4;
constexpr int A_EL = MT * KT;               // 4096 floats (16 KB)
constexpr int B_EL = NT * KT;               // 8192 floats (32 KB)
constexpr int STAGE_EL = A_EL + B_EL;       // 12288 floats (48 KB)
constexpr int SMEM_BYTES = STAGES * STAGE_EL * 4;  // 196608

// XOR swizzle in 16B chunks: float index of logical (row m, col k), k in [0,32)
__device__ __forceinline__ int swz(int m, int k) {
    return m * 32 + ((((k >> 2) ^ (m & 7)) << 2) | (k & 3));
}

template <int MODE>
__global__ void __launch_bounds__(256, 1) gemm_tf32_kernel(
    const float* __restrict__ xin,
    const float* __restrict__ W0,
    const float* __restrict__ W1,
    const float* __restrict__ W2,
    float* __restrict__ out) {
    extern __shared__ float sm[];
    const uint32_t smb = smem_u32(sm);
    const int tid  = threadIdx.x;
    const int lane = tid & 31, gid = lane >> 2, tig = lane & 3;
    const int wid  = tid >> 5, wm = wid & 1, wn = wid >> 1;

    const int m0 = blockIdx.x * MT;     // x = M (inner) -> wave shares B in L2
    const int n0 = blockIdx.y * NT;

    const float* Ap;
    const float* Bp;
    if (MODE == 0) {
        Ap = xin;
        const int ws = n0 >> 11;        // NT=256 never straddles a 2048 plane
        const float* W = (ws == 0) ? W0 : ((ws == 1) ? W1 : W2);
        Bp = W + (size_t)(n0 & (DD - 1)) * DD;
    } else {
        Ap = g_xg;
        Bp = W0 + (size_t)n0 * DD;
    }
    Ap += (size_t)m0 * DD;

    auto issue = [&](int s) {
        const int k0 = s * KT;
        const uint32_t sb = smb + (uint32_t)((s & (STAGES - 1)) * STAGE_EL * 4);
#pragma unroll
        for (int i = 0; i < 4; i++) {                 // A: 128 rows x 8 chunks
            const int idx = tid + i * 256;
            const int row = idx >> 3, ch = idx & 7;
            const float* src = Ap + (size_t)row * DD + k0 + ch * 4;
            const uint32_t dst = sb + row * 128 + (((uint32_t)(ch ^ (row & 7))) << 4);
            CP_ASYNC16(dst, src);
        }
#pragma unroll
        for (int i = 0; i < 8; i++) {                 // B: 256 rows x 8 chunks
            const int idx = tid + i * 256;
            const int row = idx >> 3, ch = idx & 7;
            const float* src = Bp + (size_t)row * DD + k0 + ch * 4;
            const uint32_t dst = sb + A_EL * 4 + row * 128 +
                                 (((uint32_t)(ch ^ (row & 7))) << 4);
            CP_ASYNC16(dst, src);
        }
        CP_COMMIT();
    };

    float c[4][8][4];
#pragma unroll
    for (int i = 0; i < 4; i++)
#pragma unroll
        for (int j = 0; j < 8; j++)
#pragma unroll
            for (int q = 0; q < 4; q++) c[i][j][q] = 0.0f;

    issue(0); issue(1); issue(2);

    for (int s = 0; s < NSLAB; s++) {
        CP_WAIT(2);
        __syncthreads();
        if (s + 3 < NSLAB) issue(s + 3);

        const float* As = sm + (s & (STAGES - 1)) * STAGE_EL;
        const float* Bs = As + A_EL;
#pragma unroll
        for (int ks = 0; ks < 4; ks++) {
            uint32_t af[4][4], bf[8][2];
            const int k = ks * 8 + tig;
#pragma unroll
            for (int mt = 0; mt < 4; mt++) {
                const int r = wm * 64 + mt * 16 + gid;
                af[mt][0] = cvt_tf32(As[swz(r,     k)]);
                af[mt][1] = cvt_tf32(As[swz(r + 8, k)]);
                af[mt][2] = cvt_tf32(As[swz(r,     k + 4)]);
                af[mt][3] = cvt_tf32(As[swz(r + 8, k + 4)]);
            }
#pragma unroll
            for (int nt = 0; nt < 8; nt++) {
                const int r = wn * 64 + nt * 8 + gid;
                bf[nt][0] = cvt_tf32(Bs[swz(r, k)]);
                bf[nt][1] = cvt_tf32(Bs[swz(r, k + 4)]);
            }
#pragma unroll
            for (int mt = 0; mt < 4; mt++)
#pragma unroll
                for (int nt = 0; nt < 8; nt++)
                    mma8(c[mt][nt], af[mt], bf[nt]);
        }
    }

    // Epilogue: c[mt][nt] covers rows (gid, gid+8), cols (2tig, 2tig+1)
#pragma unroll
    for (int mt = 0; mt < 4; mt++) {
        const int r1 = m0 + wm * 64 + mt * 16 + gid;
        const int r2 = r1 + 8;
        float s1 = 1.0f, s2 = 1.0f;
        if (MODE == 1) {
            s1 = rsqrtf(g_sumsq[r1] * (1.0f / DD) + 1e-5f);
            s2 = rsqrtf(g_sumsq[r2] * (1.0f / DD) + 1e-5f);
        }
#pragma unroll
        for (int nt = 0; nt < 8; nt++) {
            const int cg = n0 + wn * 64 + nt * 8 + 2 * tig;
            if (MODE == 0) {
                float* base = g_proj + (size_t)(cg >> 11) * PLANE + (cg & (DD - 1));
                *reinterpret_cast<float2*>(base + (size_t)r1 * DD) =
                    make_float2(c[mt][nt][0], c[mt][nt][1]);
                *reinterpret_cast<float2*>(base + (size_t)r2 * DD) =
                    make_float2(c[mt][nt][2], c[mt][nt][3]);
            } else {
                *reinterpret_cast<float2*>(out + (size_t)r1 * DD + cg) =
                    make_float2(c[mt][nt][0] * s1, c[mt][nt][1] * s1);
                *reinterpret_cast<float2*>(out + (size_t)r2 * DD + cg) =
                    make_float2(c[mt][nt][2] * s2, c[mt][nt][3] * s2);
            }
        }
    }
}

// ---------------------------------------------------------------------------
// Scan: h_t = a_t h_{t-1} + b_t; a = sigmoid(f), b = silu(i)(1-a)
// ---------------------------------------------------------------------------
__device__ __forceinline__ float sigmoidf_(float v) {
    return 1.0f / (1.0f + __expf(-v));
}

__global__ void __launch_bounds__(256) scan_chunk_kernel() {
    const int gid = blockIdx.x * 256 + threadIdx.x;   // (b, c, d)
    const int d = gid & (DD - 1);
    const int c = (gid >> 11) & (NCH - 1);
    const int b = gid >> 15;
    const size_t rb = ((size_t)(b * SS + c * TC)) * DD + d;
    const float* Ip = g_proj + rb;
    const float* Fp = g_proj + PLANE + rb;
    float A = 1.0f, Bc = 0.0f;
#pragma unroll 4
    for (int t = 0; t < TC; t++) {
        const float iv = Ip[(size_t)t * DD];
        const float fv = Fp[(size_t)t * DD];
        const float a = sigmoidf_(fv);
        const float bt = iv * sigmoidf_(iv) * (1.0f - a);
        A *= a;
        Bc = fmaf(a, Bc, bt);
    }
    g_carryA[gid] = A;
    g_carryB[gid] = Bc;
}

__global__ void __launch_bounds__(256) scan_prefix_kernel() {
    const int id = blockIdx.x * 256 + threadIdx.x;    // (b, d)
    const int d = id & (DD - 1);
    const int b = id >> 11;
    float h = 0.0f;
#pragma unroll
    for (int c = 0; c < NCH; c++) {
        const int idx = ((b * NCH) + c) * DD + d;
        g_h0[idx] = h;
        h = fmaf(g_carryA[idx], h, g_carryB[idx]);
    }
}

__global__ void __launch_bounds__(256) scan_apply_kernel(const float* __restrict__ w_norm) {
    const int gid = blockIdx.x * 256 + threadIdx.x;
    const int d = gid & (DD - 1);
    const int c = (gid >> 11) & (NCH - 1);
    const int b = gid >> 15;
    const int lane = threadIdx.x & 31;
    const size_t rb = ((size_t)(b * SS + c * TC)) * DD + d;
    const float* Ip = g_proj + rb;
    const float* Fp = g_proj + PLANE + rb;
    const float* Gp = g_proj + 2 * PLANE + rb;
    float* Xp = g_xg + rb;
    float h = g_h0[gid];
    const float wn = w_norm[d];
    const int prow0 = b * SS + c * TC;
    const int pcol = d >> 5;                          // 0..63
    for (int t = 0; t < TC; t++) {
        const float iv = Ip[(size_t)t * DD];
        const float fv = Fp[(size_t)t * DD];
        const float gv = Gp[(size_t)t * DD];
        const float a = sigmoidf_(fv);
        h = fmaf(a, h, iv * sigmoidf_(iv) * (1.0f - a));
        const float xg = h * (gv * sigmoidf_(gv));
        float ssv = xg * xg;
#pragma unroll
        for (int o = 16; o; o >>= 1) ssv += __shfl_xor_sync(0xffffffffu, ssv, o);
        if (lane == 0) g_part[(size_t)(prow0 + t) * 64 + pcol] = ssv;
        Xp[(size_t)t * DD] = xg * wn;
    }
}

__global__ void __launch_bounds__(256) sumsq_reduce_kernel() {
    const int r = blockIdx.x * 256 + threadIdx.x;     // 16384 rows
    const float4* p = reinterpret_cast<const float4*>(g_part + (size_t)r * 64);
    float s = 0.0f;
#pragma unroll
    for (int i = 0; i < 16; i++) {
        float4 v = p[i];
        s += (v.x + v.y) + (v.z + v.w);
    }
    g_sumsq[r] = s;
}

// ---------------------------------------------------------------------------
// Launcher
// ---------------------------------------------------------------------------
extern "C" void kernel_launch(void* const* d_in, const int* in_sizes, int n_in,
                              void* d_out, int out_size) {
    const float* x  = (const float*)d_in[0];
    const float* Wi = (const float*)d_in[1];
    const float* Wf = (const float*)d_in[2];
    const float* Wg = (const float*)d_in[3];
    const float* wn = (const float*)d_in[4];
    const float* Wo = (const float*)d_in[5];
    float* out = (float*)d_out;

    cudaFuncSetAttribute(gemm_tf32_kernel<0>,
                         cudaFuncAttributeMaxDynamicSharedMemorySize, SMEM_BYTES);
    cudaFuncSetAttribute(gemm_tf32_kernel<1>,
                         cudaFuncAttributeMaxDynamicSharedMemorySize, SMEM_BYTES);

    // 1) Fused projection GEMM over concatenated N = 6144 (i | f | g)
    dim3 g1(RM / MT, 3 * DD / NT);   // (128, 24)
    gemm_tf32_kernel<0><<<g1, 256, SMEM_BYTES>>>(x, Wi, Wf, Wg, nullptr);

    // 2) Chunked linear scan + RMS statistics
    scan_chunk_kernel<<<(BB * NCH * DD) / 256, 256>>>();
    scan_prefix_kernel<<<(BB * DD) / 256, 256>>>();
    scan_apply_kernel<<<(BB * NCH * DD) / 256, 256>>>(wn);
    sumsq_reduce_kernel<<<RM / 256, 256>>>();

    // 3) Output GEMM with fused RMSNorm row scaling
    dim3 g2(RM / MT, DD / NT);       // (128, 8)
    gemm_tf32_kernel<1><<<g2, 256, SMEM_BYTES>>>(nullptr, Wo, nullptr, nullptr, out);
}

// round 3
// speedup vs baseline: 2.3160x; 2.3160x over previous
#include <cuda_runtime.h>
#include <cuda_fp16.h>
#include <cstdint>

// ============================================================================
// Problem: x[4, 4096, 2048]; Wi/Wf/Wg/Wo [2048, 2048]; w_norm [2048]; fp32.
// Pipeline: fp32->fp16 convert -> GEMM(i|f|g) -> chunked linear scan ->
//           gated RMS stats -> GEMM(out) with fused row-scale.
// Tensor path: legacy mma.sync.m16n8k16 fp16 (2x MAC/instr vs tf32 m16n8k8,
// which R2 showed is the binding floor at ~256 MAC/cyc/SM).
// ============================================================================
constexpr int BB = 4;
constexpr int SS = 4096;
constexpr int DD = 2048;
constexpr int RM = BB * SS;                 // 16384 rows
constexpr size_t PLANE = (size_t)RM * DD;   // 33,554,432 elements

constexpr int TC  = 128;                    // scan chunk length
constexpr int NCH = SS / TC;                // 32 chunks

// ---------------------------------------------------------------------------
// Device scratch (static; allocations are forbidden)
// ---------------------------------------------------------------------------
__device__ float  g_proj[3 * PLANE];        // i, f, g planes (fp32)
__device__ __half g_xh[PLANE];              // x in fp16
__device__ __half g_wh[3 * (size_t)DD * DD];// Wi|Wf|Wg in fp16 (concat rows)
__device__ __half g_woh[(size_t)DD * DD];   // Wo in fp16
__device__ __half g_xgh[PLANE];             // xg * w_norm in fp16 (GEMM2 A)
__device__ float  g_carryA[BB * NCH * DD];
__device__ float  g_carryB[BB * NCH * DD];
__device__ float  g_h0[BB * NCH * DD];
__device__ float  g_part[(size_t)RM * 64];  // per-row per-warp sumsq partials
__device__ float  g_sumsq[RM];

// ---------------------------------------------------------------------------
// PTX helpers (sm_80-era only — safe under virtual arch compute_103)
// ---------------------------------------------------------------------------
__device__ __forceinline__ uint32_t smem_u32(const void* p) {
    uint32_t a;
    asm("{ .reg .u64 t; cvta.to.shared.u64 t, %1; cvt.u32.u64 %0, t; }"
        : "=r"(a) : "l"(p));
    return a;
}

#define CP_ASYNC16(dst, src) \
    asm volatile("cp.async.cg.shared.global [%0], [%1], 16;" \
                 :: "r"(dst), "l"(src))
#define CP_COMMIT() asm volatile("cp.async.commit_group;" ::: "memory")
#define CP_WAIT(n)  asm volatile("cp.async.wait_group %0;" :: "n"(n) : "memory")

// D(16x8) += A(16x16) * B(16x8), fp16 inputs, fp32 accumulate.
__device__ __forceinline__ void mma16(float* c, const uint32_t* a,
                                      uint32_t b0, uint32_t b1) {
    asm volatile(
        "mma.sync.aligned.m16n8k16.row.col.f32.f16.f16.f32 "
        "{%0,%1,%2,%3}, {%4,%5,%6,%7}, {%8,%9}, {%0,%1,%2,%3};"
        : "+f"(c[0]), "+f"(c[1]), "+f"(c[2]), "+f"(c[3])
        : "r"(a[0]), "r"(a[1]), "r"(a[2]), "r"(a[3]), "r"(b0), "r"(b1));
}

// ---------------------------------------------------------------------------
// fp16 GEMM: C[m,n] = sum_k A[m,k]*B[n,k], A,B row-major fp16.
// CTA tile 128x256x64, 256 threads, 8 warps of 64x64, 4-stage cp.async.
// MODE 0: A=g_xh, B=g_wh (i|f|g concat); writes fp32 i/f/g planes.
// MODE 1: A=g_xgh, B=g_woh; epilogue scales each row by rsqrt(mean sumsq+eps).
// ---------------------------------------------------------------------------
constexpr int MT = 128, NT = 256, KT = 64;
constexpr int NSLAB  = DD / KT;             // 32
constexpr int STAGES = 4;
constexpr int A_BYTES = MT * KT * 2;        // 16 KB (rows of 128 B)
constexpr int B_BYTES = NT * KT * 2;        // 32 KB
constexpr int STAGE_BYTES = A_BYTES + B_BYTES;       // 48 KB
constexpr int SMEM_BYTES  = STAGES * STAGE_BYTES;    // 192 KB

// smem layout: row m has 64 halves (128 B) as 8 16-byte chunks; chunk ch of
// row m lands at byte m*128 + ((ch ^ (m&7)) << 4). Conflict-free for both the
// cp.async stores and the fragment LDS.32 reads (verified by bank arithmetic).
__device__ __forceinline__ uint32_t ld_s32(const char* p) {
    return *reinterpret_cast<const uint32_t*>(p);
}

template <int MODE>
__global__ void __launch_bounds__(256, 1) gemm_f16_kernel(float* __restrict__ out) {
    extern __shared__ char sm[];
    const uint32_t smb = smem_u32(sm);
    const int tid  = threadIdx.x;
    const int lane = tid & 31, gid = lane >> 2, tig = lane & 3;
    const int wid  = tid >> 5, wm = wid & 1, wn = wid >> 1;

    const int m0 = blockIdx.x * MT;     // M fastest -> wave shares B in L2
    const int n0 = blockIdx.y * NT;

    const __half* Ap = (MODE == 0 ? g_xh : g_xgh) + (size_t)m0 * DD;
    const __half* Bp = (MODE == 0 ? g_wh : g_woh) + (size_t)n0 * DD;

    auto issue = [&](int s) {
        const int k0 = s * KT;
        const uint32_t sb = smb + (uint32_t)((s & (STAGES - 1)) * STAGE_BYTES);
#pragma unroll
        for (int i = 0; i < 4; i++) {                 // A: 128 rows x 8 chunks
            const int idx = tid + i * 256;
            const int row = idx >> 3, ch = idx & 7;
            CP_ASYNC16(sb + row * 128 + (((uint32_t)(ch ^ (row & 7))) << 4),
                       Ap + (size_t)row * DD + k0 + ch * 8);
        }
#pragma unroll
        for (int i = 0; i < 8; i++) {                 // B: 256 rows x 8 chunks
            const int idx = tid + i * 256;
            const int row = idx >> 3, ch = idx & 7;
            CP_ASYNC16(sb + A_BYTES + row * 128 +
                           (((uint32_t)(ch ^ (row & 7))) << 4),
                       Bp + (size_t)row * DD + k0 + ch * 8);
        }
        CP_COMMIT();
    };

    float c[4][8][4];
#pragma unroll
    for (int i = 0; i < 4; i++)
#pragma unroll
        for (int j = 0; j < 8; j++)
#pragma unroll
            for (int q = 0; q < 4; q++) c[i][j][q] = 0.0f;

    issue(0); issue(1); issue(2);

    for (int s = 0; s < NSLAB; s++) {
        CP_WAIT(2);
        __syncthreads();
        if (s + 3 < NSLAB) issue(s + 3);

        const char* As = sm + (s & (STAGES - 1)) * STAGE_BYTES;
        const char* Bs = As + A_BYTES;
#pragma unroll
        for (int ks = 0; ks < 4; ks++) {              // 4 x K16 = KT 64
            // fragment k-coords: lo chunk = 2ks, hi chunk = 2ks+1, inner 2*tig
            uint32_t af[4][4], bf[8][2];
#pragma unroll
            for (int mt = 0; mt < 4; mt++) {
                const int r = wm * 64 + mt * 16 + gid;
                const int rc0 = ((2 * ks)     ^ (r & 7))       << 4;
                const int rc1 = ((2 * ks + 1) ^ (r & 7))       << 4;
                const int sc0 = ((2 * ks)     ^ ((r + 8) & 7)) << 4;
                const int sc1 = ((2 * ks + 1) ^ ((r + 8) & 7)) << 4;
                af[mt][0] = ld_s32(As + r * 128       + rc0 + tig * 4);
                af[mt][1] = ld_s32(As + (r + 8) * 128 + sc0 + tig * 4);
                af[mt][2] = ld_s32(As + r * 128       + rc1 + tig * 4);
                af[mt][3] = ld_s32(As + (r + 8) * 128 + sc1 + tig * 4);
            }
#pragma unroll
            for (int nt = 0; nt < 8; nt++) {
                const int r = wn * 64 + nt * 8 + gid;
                const int rc0 = ((2 * ks)     ^ (r & 7)) << 4;
                const int rc1 = ((2 * ks + 1) ^ (r & 7)) << 4;
                bf[nt][0] = ld_s32(Bs + r * 128 + rc0 + tig * 4);
                bf[nt][1] = ld_s32(Bs + r * 128 + rc1 + tig * 4);
            }
#pragma unroll
            for (int mt = 0; mt < 4; mt++)
#pragma unroll
                for (int nt = 0; nt < 8; nt++)
                    mma16(c[mt][nt], af[mt], bf[nt][0], bf[nt][1]);
        }
    }

    // Epilogue: c[mt][nt] covers rows (gid, gid+8), cols (2tig, 2tig+1)
#pragma unroll
    for (int mt = 0; mt < 4; mt++) {
        const int r1 = m0 + wm * 64 + mt * 16 + gid;
        const int r2 = r1 + 8;
        float s1 = 1.0f, s2 = 1.0f;
        if (MODE == 1) {
            s1 = rsqrtf(g_sumsq[r1] * (1.0f / DD) + 1e-5f);
            s2 = rsqrtf(g_sumsq[r2] * (1.0f / DD) + 1e-5f);
        }
#pragma unroll
        for (int nt = 0; nt < 8; nt++) {
            const int cg = n0 + wn * 64 + nt * 8 + 2 * tig;
            if (MODE == 0) {
                float* base = g_proj + (size_t)(cg >> 11) * PLANE + (cg & (DD - 1));
                *reinterpret_cast<float2*>(base + (size_t)r1 * DD) =
                    make_float2(c[mt][nt][0], c[mt][nt][1]);
                *reinterpret_cast<float2*>(base + (size_t)r2 * DD) =
                    make_float2(c[mt][nt][2], c[mt][nt][3]);
            } else {
                *reinterpret_cast<float2*>(out + (size_t)r1 * DD + cg) =
                    make_float2(c[mt][nt][0] * s1, c[mt][nt][1] * s1);
                *reinterpret_cast<float2*>(out + (size_t)r2 * DD + cg) =
                    make_float2(c[mt][nt][2] * s2, c[mt][nt][3] * s2);
            }
        }
    }
}

// ---------------------------------------------------------------------------
// fp32 -> fp16 conversion (vectorized, grid-stride-free: exact cover)
// ---------------------------------------------------------------------------
__global__ void __launch_bounds__(256) f2h_kernel(const float* __restrict__ src,
                                                  __half* __restrict__ dst) {
    const size_t i = ((size_t)blockIdx.x * 256 + threadIdx.x) * 8;
    float4 v0 = *reinterpret_cast<const float4*>(src + i);
    float4 v1 = *reinterpret_cast<const float4*>(src + i + 4);
    __half2 h[4];
    h[0] = __floats2half2_rn(v0.x, v0.y);
    h[1] = __floats2half2_rn(v0.z, v0.w);
    h[2] = __floats2half2_rn(v1.x, v1.y);
    h[3] = __floats2half2_rn(v1.z, v1.w);
    *reinterpret_cast<uint4*>(dst + i) = *reinterpret_cast<uint4*>(h);
}

// ---------------------------------------------------------------------------
// Scan: h_t = a_t h_{t-1} + b_t; a = sigmoid(f), b = silu(i)(1-a)
// ---------------------------------------------------------------------------
__device__ __forceinline__ float sigmoidf_(float v) {
    return 1.0f / (1.0f + __expf(-v));
}

__global__ void __launch_bounds__(256) scan_chunk_kernel() {
    const int gid = blockIdx.x * 256 + threadIdx.x;   // (b, c, d)
    const int d = gid & (DD - 1);
    const int c = (gid >> 11) & (NCH - 1);
    const int b = gid >> 16;                          // 11 + 5
    const size_t rb = ((size_t)(b * SS + c * TC)) * DD + d;
    const float* Ip = g_proj + rb;
    const float* Fp = g_proj + PLANE + rb;
    float A = 1.0f, Bc = 0.0f;
#pragma unroll 4
    for (int t = 0; t < TC; t++) {
        const float iv = Ip[(size_t)t * DD];
        const float fv = Fp[(size_t)t * DD];
        const float a = sigmoidf_(fv);
        const float bt = iv * sigmoidf_(iv) * (1.0f - a);
        A *= a;
        Bc = fmaf(a, Bc, bt);
    }
    g_carryA[gid] = A;
    g_carryB[gid] = Bc;
}

__global__ void __launch_bounds__(256) scan_prefix_kernel() {
    const int id = blockIdx.x * 256 + threadIdx.x;    // (b, d)
    const int d = id & (DD - 1);
    const int b = id >> 11;
    float h = 0.0f;
#pragma unroll
    for (int c = 0; c < NCH; c++) {
        const int idx = ((b * NCH) + c) * DD + d;
        g_h0[idx] = h;
        h = fmaf(g_carryA[idx], h, g_carryB[idx]);
    }
}

__global__ void __launch_bounds__(256) scan_apply_kernel(const float* __restrict__ w_norm) {
    const int gid = blockIdx.x * 256 + threadIdx.x;
    const int d = gid & (DD - 1);
    const int c = (gid >> 11) & (NCH - 1);
    const int b = gid >> 16;
    const int lane = threadIdx.x & 31;
    const size_t rb = ((size_t)(b * SS + c * TC)) * DD + d;
    const float* Ip = g_proj + rb;
    const float* Fp = g_proj + PLANE + rb;
    const float* Gp = g_proj + 2 * PLANE + rb;
    __half* Xp = g_xgh + rb;
    float h = g_h0[gid];
    const float wn = w_norm[d];
    const int prow0 = b * SS + c * TC;
    const int pcol = d >> 5;                          // 0..63
    for (int t = 0; t < TC; t++) {
        const float iv = Ip[(size_t)t * DD];
        const float fv = Fp[(size_t)t * DD];
        const float gv = Gp[(size_t)t * DD];
        const float a = sigmoidf_(fv);
        h = fmaf(a, h, iv * sigmoidf_(iv) * (1.0f - a));
        const float xg = h * (gv * sigmoidf_(gv));
        float ssv = xg * xg;
#pragma unroll
        for (int o = 16; o; o >>= 1) ssv += __shfl_xor_sync(0xffffffffu, ssv, o);
        if (lane == 0) g_part[(size_t)(prow0 + t) * 64 + pcol] = ssv;
        Xp[(size_t)t * DD] = __float2half_rn(xg * wn);
    }
}

__global__ void __launch_bounds__(256) sumsq_reduce_kernel() {
    const int r = blockIdx.x * 256 + threadIdx.x;     // 16384 rows
    const float4* p = reinterpret_cast<const float4*>(g_part + (size_t)r * 64);
    float s = 0.0f;
#pragma unroll
    for (int i = 0; i < 16; i++) {
        float4 v = p[i];
        s += (v.x + v.y) + (v.z + v.w);
    }
    g_sumsq[r] = s;
}

// ---------------------------------------------------------------------------
// Launcher
// ---------------------------------------------------------------------------
extern "C" void kernel_launch(void* const* d_in, const int* in_sizes, int n_in,
                              void* d_out, int out_size) {
    const float* x  = (const float*)d_in[0];
    const float* Wi = (const float*)d_in[1];
    const float* Wf = (const float*)d_in[2];
    const float* Wg = (const float*)d_in[3];
    const float* wn = (const float*)d_in[4];
    const float* Wo = (const float*)d_in[5];
    float* out = (float*)d_out;

    cudaFuncSetAttribute(gemm_f16_kernel<0>,
                         cudaFuncAttributeMaxDynamicSharedMemorySize, SMEM_BYTES);
    cudaFuncSetAttribute(gemm_f16_kernel<1>,
                         cudaFuncAttributeMaxDynamicSharedMemorySize, SMEM_BYTES);

    __half* xh;  cudaGetSymbolAddress((void**)&xh,  g_xh);
    __half* wh;  cudaGetSymbolAddress((void**)&wh,  g_wh);
    __half* woh; cudaGetSymbolAddress((void**)&woh, g_woh);

    // 0) fp32 -> fp16 conversions
    constexpr int WEL = DD * DD;             // 4,194,304
    f2h_kernel<<<PLANE / 2048, 256>>>(x, xh);
    f2h_kernel<<<WEL / 2048, 256>>>(Wi, wh);
    f2h_kernel<<<WEL / 2048, 256>>>(Wf, wh + (size_t)WEL);
    f2h_kernel<<<WEL / 2048, 256>>>(Wg, wh + 2 * (size_t)WEL);
    f2h_kernel<<<WEL / 2048, 256>>>(Wo, woh);

    // 1) Fused projection GEMM over concatenated N = 6144 (i | f | g)
    dim3 g1(RM / MT, 3 * DD / NT);   // (128, 24)
    gemm_f16_kernel<0><<<g1, 256, SMEM_BYTES>>>(nullptr);

    // 2) Chunked linear scan + RMS statistics
    scan_chunk_kernel<<<(BB * NCH * DD) / 256, 256>>>();
    scan_prefix_kernel<<<(BB * DD) / 256, 256>>>();
    scan_apply_kernel<<<(BB * NCH * DD) / 256, 256>>>(wn);
    sumsq_reduce_kernel<<<RM / 256, 256>>>();

    // 3) Output GEMM with fused RMSNorm row scaling
    dim3 g2(RM / MT, DD / NT);       // (128, 8)
    gemm_f16_kernel<1><<<g2, 256, SMEM_BYTES>>>(out);
}

// round 4
// speedup vs baseline: 2.4363x; 1.0519x over previous
#include <cuda_runtime.h>
#include <cuda_fp16.h>
#include <cstdint>

// ============================================================================
// Problem: x[4, 4096, 2048]; Wi/Wf/Wg/Wo [2048, 2048]; w_norm [2048]; fp32.
// Pipeline: fp32->fp16 convert -> fp16 GEMM(i|f|g, fp16 planes) ->
//           latency-hidden chunked linear scan -> gated RMS stats ->
//           fp16 GEMM(out) with fused row-scale epilogue.
// ============================================================================
constexpr int BB = 4;
constexpr int SS = 4096;
constexpr int DD = 2048;
constexpr int RM = BB * SS;                 // 16384 rows
constexpr size_t PLANE = (size_t)RM * DD;   // 33,554,432 elements

constexpr int TC  = 128;                    // scan chunk length
constexpr int NCH = SS / TC;                // 32 chunks

// ---------------------------------------------------------------------------
// Device scratch (static; allocations are forbidden)
// ---------------------------------------------------------------------------
__device__ __half g_proj[3 * PLANE];        // i, f, g planes (fp16)
__device__ __half g_xh[PLANE];              // x in fp16
__device__ __half g_wh[3 * (size_t)DD * DD];// Wi|Wf|Wg in fp16 (concat rows)
__device__ __half g_woh[(size_t)DD * DD];   // Wo in fp16
__device__ __half g_xgh[PLANE];             // xg * w_norm in fp16 (GEMM2 A)
__device__ float  g_carryA[BB * NCH * DD];
__device__ float  g_carryB[BB * NCH * DD];
__device__ float  g_h0[BB * NCH * DD];
__device__ float  g_part[(size_t)RM * 64];  // per-row per-warp sumsq partials
__device__ float  g_sumsq[RM];

// ---------------------------------------------------------------------------
// PTX helpers (sm_80-era only — safe under virtual arch compute_103)
// ---------------------------------------------------------------------------
__device__ __forceinline__ uint32_t smem_u32(const void* p) {
    uint32_t a;
    asm("{ .reg .u64 t; cvta.to.shared.u64 t, %1; cvt.u32.u64 %0, t; }"
        : "=r"(a) : "l"(p));
    return a;
}

#define CP_ASYNC16(dst, src) \
    asm volatile("cp.async.cg.shared.global [%0], [%1], 16;" \
                 :: "r"(dst), "l"(src))
#define CP_COMMIT() asm volatile("cp.async.commit_group;" ::: "memory")
#define CP_WAIT(n)  asm volatile("cp.async.wait_group %0;" :: "n"(n) : "memory")

__device__ __forceinline__ void ldsm4(uint32_t& r0, uint32_t& r1,
                                      uint32_t& r2, uint32_t& r3, uint32_t a) {
    asm volatile("ldmatrix.sync.aligned.m8n8.x4.shared.b16 {%0,%1,%2,%3}, [%4];"
                 : "=r"(r0), "=r"(r1), "=r"(r2), "=r"(r3) : "r"(a));
}

// D(16x8) += A(16x16) * B(16x8), fp16 inputs, fp32 accumulate.
__device__ __forceinline__ void mma16(float* c, const uint32_t* a,
                                      uint32_t b0, uint32_t b1) {
    asm volatile(
        "mma.sync.aligned.m16n8k16.row.col.f32.f16.f16.f32 "
        "{%0,%1,%2,%3}, {%4,%5,%6,%7}, {%8,%9}, {%0,%1,%2,%3};"
        : "+f"(c[0]), "+f"(c[1]), "+f"(c[2]), "+f"(c[3])
        : "r"(a[0]), "r"(a[1]), "r"(a[2]), "r"(a[3]), "r"(b0), "r"(b1));
}

// ---------------------------------------------------------------------------
// fp16 GEMM: C[m,n] = sum_k A[m,k]*B[n,k], A,B row-major fp16.
// CTA tile 128x256x64, 256 threads, 8 warps of 64x64, 4-stage cp.async,
// ldmatrix.x4 fragment loads.
// MODE 0: A=g_xh, B=g_wh (i|f|g concat); writes fp16 i/f/g planes.
// MODE 1: A=g_xgh, B=g_woh; epilogue scales each row by rsqrt(mean sumsq+eps).
// ---------------------------------------------------------------------------
constexpr int MT = 128, NT = 256, KT = 64;
constexpr int NSLAB  = DD / KT;             // 32
constexpr int STAGES = 4;
constexpr int A_BYTES = MT * KT * 2;        // 16 KB (rows of 128 B)
constexpr int B_BYTES = NT * KT * 2;        // 32 KB
constexpr int STAGE_BYTES = A_BYTES + B_BYTES;       // 48 KB
constexpr int SMEM_BYTES  = STAGES * STAGE_BYTES;    // 192 KB

// smem: row m = 64 halves (128 B) as 8 16-byte chunks; chunk ch of row m at
// byte m*128 + ((ch ^ (m&7)) << 4). Conflict-free for cp.async stores and for
// ldmatrix (8 consecutive rows -> 8 distinct chunk slots via the XOR).

template <int MODE>
__global__ void __launch_bounds__(256, 1) gemm_f16_kernel(float* __restrict__ out) {
    extern __shared__ char sm[];
    const uint32_t smb = smem_u32(sm);
    const int tid  = threadIdx.x;
    const int lane = tid & 31, gid = lane >> 2, tig = lane & 3;
    const int wid  = tid >> 5, wm = wid & 1, wn = wid >> 1;

    const int m0 = blockIdx.x * MT;     // M fastest -> wave shares B in L2
    const int n0 = blockIdx.y * NT;

    const __half* Ap = (MODE == 0 ? g_xh : g_xgh) + (size_t)m0 * DD;
    const __half* Bp = (MODE == 0 ? g_wh : g_woh) + (size_t)n0 * DD;

    auto issue = [&](int s) {
        const int k0 = s * KT;
        const uint32_t sb = smb + (uint32_t)((s & (STAGES - 1)) * STAGE_BYTES);
#pragma unroll
        for (int i = 0; i < 4; i++) {                 // A: 128 rows x 8 chunks
            const int idx = tid + i * 256;
            const int row = idx >> 3, ch = idx & 7;
            CP_ASYNC16(sb + row * 128 + (((uint32_t)(ch ^ (row & 7))) << 4),
                       Ap + (size_t)row * DD + k0 + ch * 8);
        }
#pragma unroll
        for (int i = 0; i < 8; i++) {                 // B: 256 rows x 8 chunks
            const int idx = tid + i * 256;
            const int row = idx >> 3, ch = idx & 7;
            CP_ASYNC16(sb + A_BYTES + row * 128 +
                           (((uint32_t)(ch ^ (row & 7))) << 4),
                       Bp + (size_t)row * DD + k0 + ch * 8);
        }
        CP_COMMIT();
    };

    // Per-lane ldmatrix row assignments (fixed across the k loop)
    const int sel = lane >> 3, ro = lane & 7;
    // A: matrices (rows r0..r0+7, c0), (r0+8.., c0), (r0.., c1), (r0+8.., c1)
    const int a_row_off = ((sel & 1) << 3) + ro;      // + mt*16 + wm*64
    const int a_cbit    = sel >> 1;
    // B: matrices (n0..n0+7, c0), (n0.., c1), (n0+8.., c0), (n0+8.., c1)
    const int b_row_off = ((sel >> 1) << 3) + ro;     // + ntp*16 + wn*64
    const int b_cbit    = sel & 1;

    float c[4][8][4];
#pragma unroll
    for (int i = 0; i < 4; i++)
#pragma unroll
        for (int j = 0; j < 8; j++)
#pragma unroll
            for (int q = 0; q < 4; q++) c[i][j][q] = 0.0f;

    issue(0); issue(1); issue(2);

    for (int s = 0; s < NSLAB; s++) {
        CP_WAIT(2);
        __syncthreads();
        if (s + 3 < NSLAB) issue(s + 3);

        const uint32_t As = smb + (s & (STAGES - 1)) * STAGE_BYTES;
        const uint32_t Bs = As + A_BYTES;
#pragma unroll
        for (int ks = 0; ks < 4; ks++) {              // 4 x K16 = KT 64
            uint32_t af[4][4], bf[8][2];
#pragma unroll
            for (int mt = 0; mt < 4; mt++) {
                const int row = wm * 64 + mt * 16 + a_row_off;
                const int ch  = (2 * ks + a_cbit) ^ (row & 7);
                ldsm4(af[mt][0], af[mt][1], af[mt][2], af[mt][3],
                      As + row * 128 + (ch << 4));
            }
#pragma unroll
            for (int ntp = 0; ntp < 4; ntp++) {
                const int row = wn * 64 + ntp * 16 + b_row_off;
                const int ch  = (2 * ks + b_cbit) ^ (row & 7);
                ldsm4(bf[2 * ntp][0], bf[2 * ntp][1],
                      bf[2 * ntp + 1][0], bf[2 * ntp + 1][1],
                      Bs + row * 128 + (ch << 4));
            }
#pragma unroll
            for (int mt = 0; mt < 4; mt++)
#pragma unroll
                for (int nt = 0; nt < 8; nt++)
                    mma16(c[mt][nt], af[mt], bf[nt][0], bf[nt][1]);
        }
    }

    // Epilogue: c[mt][nt] covers rows (gid, gid+8), cols (2tig, 2tig+1)
#pragma unroll
    for (int mt = 0; mt < 4; mt++) {
        const int r1 = m0 + wm * 64 + mt * 16 + gid;
        const int r2 = r1 + 8;
        float s1 = 1.0f, s2 = 1.0f;
        if (MODE == 1) {
            s1 = rsqrtf(g_sumsq[r1] * (1.0f / DD) + 1e-5f);
            s2 = rsqrtf(g_sumsq[r2] * (1.0f / DD) + 1e-5f);
        }
#pragma unroll
        for (int nt = 0; nt < 8; nt++) {
            const int cg = n0 + wn * 64 + nt * 8 + 2 * tig;
            if (MODE == 0) {
                __half* base = g_proj + (size_t)(cg >> 11) * PLANE + (cg & (DD - 1));
                *reinterpret_cast<__half2*>(base + (size_t)r1 * DD) =
                    __floats2half2_rn(c[mt][nt][0], c[mt][nt][1]);
                *reinterpret_cast<__half2*>(base + (size_t)r2 * DD) =
                    __floats2half2_rn(c[mt][nt][2], c[mt][nt][3]);
            } else {
                *reinterpret_cast<float2*>(out + (size_t)r1 * DD + cg) =
                    make_float2(c[mt][nt][0] * s1, c[mt][nt][1] * s1);
                *reinterpret_cast<float2*>(out + (size_t)r2 * DD + cg) =
                    make_float2(c[mt][nt][2] * s2, c[mt][nt][3] * s2);
            }
        }
    }
}

// ---------------------------------------------------------------------------
// fp32 -> fp16 conversion
// ---------------------------------------------------------------------------
__global__ void __launch_bounds__(256) f2h_kernel(const float* __restrict__ src,
                                                  __half* __restrict__ dst) {
    const size_t i = ((size_t)blockIdx.x * 256 + threadIdx.x) * 8;
    float4 v0 = *reinterpret_cast<const float4*>(src + i);
    float4 v1 = *reinterpret_cast<const float4*>(src + i + 4);
    __half2 h[4];
    h[0] = __floats2half2_rn(v0.x, v0.y);
    h[1] = __floats2half2_rn(v0.z, v0.w);
    h[2] = __floats2half2_rn(v1.x, v1.y);
    h[3] = __floats2half2_rn(v1.z, v1.w);
    *reinterpret_cast<uint4*>(dst + i) = *reinterpret_cast<uint4*>(h);
}

// ---------------------------------------------------------------------------
// Scan: h_t = a_t h_{t-1} + b_t; a = sigmoid(f), b = silu(i)(1-a)
// Loads batched in groups of 4 timesteps (MLP 8-12) to hide DRAM latency.
// ---------------------------------------------------------------------------
__device__ __forceinline__ float sigmoidf_(float v) {
    return 1.0f / (1.0f + __expf(-v));
}

__global__ void __launch_bounds__(256) scan_chunk_kernel() {
    const int gid = blockIdx.x * 256 + threadIdx.x;   // (b, c, d)
    const int d = gid & (DD - 1);
    const int c = (gid >> 11) & (NCH - 1);
    const int b = gid >> 16;                          // 11 + 5
    const size_t rb = ((size_t)(b * SS + c * TC)) * DD + d;
    const __half* Ip = g_proj + rb;
    const __half* Fp = g_proj + PLANE + rb;
    float A = 1.0f, Bc = 0.0f;
    for (int t0 = 0; t0 < TC; t0 += 4) {
        float iv[4], fv[4];
#pragma unroll
        for (int j = 0; j < 4; j++) {
            iv[j] = __half2float(Ip[(size_t)(t0 + j) * DD]);
            fv[j] = __half2float(Fp[(size_t)(t0 + j) * DD]);
        }
#pragma unroll
        for (int j = 0; j < 4; j++) {
            const float a = sigmoidf_(fv[j]);
            const float bt = iv[j] * sigmoidf_(iv[j]) * (1.0f - a);
            A *= a;
            Bc = fmaf(a, Bc, bt);
        }
    }
    g_carryA[gid] = A;
    g_carryB[gid] = Bc;
}

__global__ void __launch_bounds__(256) scan_prefix_kernel() {
    const int id = blockIdx.x * 256 + threadIdx.x;    // (b, d)
    const int d = id & (DD - 1);
    const int b = id >> 11;
    float h = 0.0f;
#pragma unroll
    for (int c = 0; c < NCH; c++) {
        const int idx = ((b * NCH) + c) * DD + d;
        g_h0[idx] = h;
        h = fmaf(g_carryA[idx], h, g_carryB[idx]);
    }
}

__global__ void __launch_bounds__(256) scan_apply_kernel(const float* __restrict__ w_norm) {
    const int gid = blockIdx.x * 256 + threadIdx.x;
    const int d = gid & (DD - 1);
    const int c = (gid >> 11) & (NCH - 1);
    const int b = gid >> 16;
    const int lane = threadIdx.x & 31;
    const size_t rb = ((size_t)(b * SS + c * TC)) * DD + d;
    const __half* Ip = g_proj + rb;
    const __half* Fp = g_proj + PLANE + rb;
    const __half* Gp = g_proj + 2 * PLANE + rb;
    __half* Xp = g_xgh + rb;
    float h = g_h0[gid];
    const float wn = w_norm[d];
    const int prow0 = b * SS + c * TC;
    const int pcol = d >> 5;                          // 0..63
    for (int t0 = 0; t0 < TC; t0 += 4) {
        float iv[4], fv[4], gv[4];
#pragma unroll
        for (int j = 0; j < 4; j++) {
            iv[j] = __half2float(Ip[(size_t)(t0 + j) * DD]);
            fv[j] = __half2float(Fp[(size_t)(t0 + j) * DD]);
            gv[j] = __half2float(Gp[(size_t)(t0 + j) * DD]);
        }
#pragma unroll
        for (int j = 0; j < 4; j++) {
            const float a = sigmoidf_(fv[j]);
            h = fmaf(a, h, iv[j] * sigmoidf_(iv[j]) * (1.0f - a));
            const float xg = h * (gv[j] * sigmoidf_(gv[j]));
            float ssv = xg * xg;
#pragma unroll
            for (int o = 16; o; o >>= 1) ssv += __shfl_xor_sync(0xffffffffu, ssv, o);
            if (lane == 0) g_part[(size_t)(prow0 + t0 + j) * 64 + pcol] = ssv;
            Xp[(size_t)(t0 + j) * DD] = __float2half_rn(xg * wn);
        }
    }
}

__global__ void __launch_bounds__(256) sumsq_reduce_kernel() {
    const int r = blockIdx.x * 256 + threadIdx.x;     // 16384 rows
    const float4* p = reinterpret_cast<const float4*>(g_part + (size_t)r * 64);
    float s = 0.0f;
#pragma unroll
    for (int i = 0; i < 16; i++) {
        float4 v = p[i];
        s += (v.x + v.y) + (v.z + v.w);
    }
    g_sumsq[r] = s;
}

// ---------------------------------------------------------------------------
// Launcher
// ---------------------------------------------------------------------------
extern "C" void kernel_launch(void* const* d_in, const int* in_sizes, int n_in,
                              void* d_out, int out_size) {
    const float* x  = (const float*)d_in[0];
    const float* Wi = (const float*)d_in[1];
    const float* Wf = (const float*)d_in[2];
    const float* Wg = (const float*)d_in[3];
    const float* wn = (const float*)d_in[4];
    const float* Wo = (const float*)d_in[5];
    float* out = (float*)d_out;

    cudaFuncSetAttribute(gemm_f16_kernel<0>,
                         cudaFuncAttributeMaxDynamicSharedMemorySize, SMEM_BYTES);
    cudaFuncSetAttribute(gemm_f16_kernel<1>,
                         cudaFuncAttributeMaxDynamicSharedMemorySize, SMEM_BYTES);

    __half* xh;  cudaGetSymbolAddress((void**)&xh,  g_xh);
    __half* wh;  cudaGetSymbolAddress((void**)&wh,  g_wh);
    __half* woh; cudaGetSymbolAddress((void**)&woh, g_woh);

    // 0) fp32 -> fp16 conversions
    constexpr int WEL = DD * DD;             // 4,194,304
    f2h_kernel<<<PLANE / 2048, 256>>>(x, xh);
    f2h_kernel<<<WEL / 2048, 256>>>(Wi, wh);
    f2h_kernel<<<WEL / 2048, 256>>>(Wf, wh + (size_t)WEL);
    f2h_kernel<<<WEL / 2048, 256>>>(Wg, wh + 2 * (size_t)WEL);
    f2h_kernel<<<WEL / 2048, 256>>>(Wo, woh);

    // 1) Fused projection GEMM over concatenated N = 6144 (i | f | g)
    dim3 g1(RM / MT, 3 * DD / NT);   // (128, 24)
    gemm_f16_kernel<0><<<g1, 256, SMEM_BYTES>>>(nullptr);

    // 2) Chunked linear scan + RMS statistics
    scan_chunk_kernel<<<(BB * NCH * DD) / 256, 256>>>();
    scan_prefix_kernel<<<(BB * DD) / 256, 256>>>();
    scan_apply_kernel<<<(BB * NCH * DD) / 256, 256>>>(wn);
    sumsq_reduce_kernel<<<RM / 256, 256>>>();

    // 3) Output GEMM with fused RMSNorm row scaling
    dim3 g2(RM / MT, DD / NT);       // (128, 8)
    gemm_f16_kernel<1><<<g2, 256, SMEM_BYTES>>>(out);
}

// round 5
// speedup vs baseline: 2.6368x; 1.0823x over previous
#include <cuda_runtime.h>
#include <cuda_fp16.h>
#include <cstdint>

// ============================================================================
// Problem: x[4, 4096, 2048]; Wi/Wf/Wg/Wo [2048, 2048]; w_norm [2048]; fp32.
// Pipeline: fp32->fp16 convert -> fp16 GEMM(i|f|g, fp16 planes) ->
//           half2 channel-paired chunked linear scan -> gated RMS stats ->
//           fp16 GEMM(out) with fused row-scale epilogue.
// GEMM: m16n8k16 HMMA, tile 128x128x64, 3-stage cp.async, 2 CTAs/SM.
// ============================================================================
constexpr int BB = 4;
constexpr int SS = 4096;
constexpr int DD = 2048;
constexpr int RM = BB * SS;                 // 16384 rows
constexpr size_t PLANE = (size_t)RM * DD;   // 33,554,432 elements

constexpr int TC  = 128;                    // scan chunk length
constexpr int NCH = SS / TC;                // 32 chunks
constexpr int DP  = DD / 2;                 // 1024 channel pairs

// ---------------------------------------------------------------------------
// Device scratch (static; allocations are forbidden)
// ---------------------------------------------------------------------------
__device__ __half g_proj[3 * PLANE];        // i, f, g planes (fp16)
__device__ __half g_xh[PLANE];              // x in fp16
__device__ __half g_wh[3 * (size_t)DD * DD];// Wi|Wf|Wg in fp16 (concat rows)
__device__ __half g_woh[(size_t)DD * DD];   // Wo in fp16
__device__ __half g_xgh[PLANE];             // xg * w_norm in fp16 (GEMM2 A)
__device__ float  g_carryA[BB * NCH * DD];
__device__ float  g_carryB[BB * NCH * DD];
__device__ float  g_h0[BB * NCH * DD];
__device__ float  g_part[(size_t)RM * 32];  // per-row per-warp sumsq partials
__device__ float  g_sumsq[RM];

// ---------------------------------------------------------------------------
// PTX helpers (sm_80-era only — safe under virtual arch compute_103)
// ---------------------------------------------------------------------------
__device__ __forceinline__ uint32_t smem_u32(const void* p) {
    uint32_t a;
    asm("{ .reg .u64 t; cvta.to.shared.u64 t, %1; cvt.u32.u64 %0, t; }"
        : "=r"(a) : "l"(p));
    return a;
}

#define CP_ASYNC16(dst, src) \
    asm volatile("cp.async.cg.shared.global [%0], [%1], 16;" \
                 :: "r"(dst), "l"(src))
#define CP_COMMIT() asm volatile("cp.async.commit_group;" ::: "memory")
#define CP_WAIT(n)  asm volatile("cp.async.wait_group %0;" :: "n"(n) : "memory")

__device__ __forceinline__ void ldsm4(uint32_t& r0, uint32_t& r1,
                                      uint32_t& r2, uint32_t& r3, uint32_t a) {
    asm volatile("ldmatrix.sync.aligned.m8n8.x4.shared.b16 {%0,%1,%2,%3}, [%4];"
                 : "=r"(r0), "=r"(r1), "=r"(r2), "=r"(r3) : "r"(a));
}

// D(16x8) += A(16x16) * B(16x8), fp16 inputs, fp32 accumulate.
__device__ __forceinline__ void mma16(float* c, const uint32_t* a,
                                      uint32_t b0, uint32_t b1) {
    asm volatile(
        "mma.sync.aligned.m16n8k16.row.col.f32.f16.f16.f32 "
        "{%0,%1,%2,%3}, {%4,%5,%6,%7}, {%8,%9}, {%0,%1,%2,%3};"
        : "+f"(c[0]), "+f"(c[1]), "+f"(c[2]), "+f"(c[3])
        : "r"(a[0]), "r"(a[1]), "r"(a[2]), "r"(a[3]), "r"(b0), "r"(b1));
}

// ---------------------------------------------------------------------------
// fp16 GEMM: C[m,n] = sum_k A[m,k]*B[n,k], A,B row-major fp16.
// CTA tile 128x128x64, 256 threads, 8 warps of 32x64, 3-stage cp.async,
// 2 CTAs/SM so sync/prologue/epilogue of one CTA overlaps the other's MMAs.
// MODE 0: A=g_xh, B=g_wh (i|f|g concat); writes fp16 i/f/g planes.
// MODE 1: A=g_xgh, B=g_woh; epilogue scales each row by rsqrt(mean sumsq+eps).
// ---------------------------------------------------------------------------
constexpr int MT = 128, NT = 128, KT = 64;
constexpr int NSLAB  = DD / KT;             // 32
constexpr int STAGES = 3;
constexpr int A_BYTES = MT * KT * 2;        // 16 KB (rows of 128 B)
constexpr int B_BYTES = NT * KT * 2;        // 16 KB
constexpr int STAGE_BYTES = A_BYTES + B_BYTES;       // 32 KB
constexpr int SMEM_BYTES  = STAGES * STAGE_BYTES;    // 96 KB

// smem: row m = 64 halves (128 B) as 8 16-byte chunks; chunk ch of row m at
// byte m*128 + ((ch ^ (m&7)) << 4). Conflict-free for cp.async stores and
// for ldmatrix reads.

template <int MODE>
__global__ void __launch_bounds__(256, 2) gemm_f16_kernel(float* __restrict__ out) {
    extern __shared__ char sm[];
    const uint32_t smb = smem_u32(sm);
    const int tid  = threadIdx.x;
    const int lane = tid & 31, gid = lane >> 2, tig = lane & 3;
    const int wid  = tid >> 5, wm = wid & 3, wn = wid >> 2;

    const int m0 = blockIdx.x * MT;     // M fastest -> wave shares B in L2
    const int n0 = blockIdx.y * NT;

    const __half* Ap = (MODE == 0 ? g_xh : g_xgh) + (size_t)m0 * DD;
    const __half* Bp = (MODE == 0 ? g_wh : g_woh) + (size_t)n0 * DD;

    auto issue = [&](int s) {
        const int k0 = s * KT;
        const uint32_t sb = smb + (uint32_t)((s % STAGES) * STAGE_BYTES);
#pragma unroll
        for (int i = 0; i < 4; i++) {                 // A: 128 rows x 8 chunks
            const int idx = tid + i * 256;
            const int row = idx >> 3, ch = idx & 7;
            CP_ASYNC16(sb + row * 128 + (((uint32_t)(ch ^ (row & 7))) << 4),
                       Ap + (size_t)row * DD + k0 + ch * 8);
        }
#pragma unroll
        for (int i = 0; i < 4; i++) {                 // B: 128 rows x 8 chunks
            const int idx = tid + i * 256;
            const int row = idx >> 3, ch = idx & 7;
            CP_ASYNC16(sb + A_BYTES + row * 128 +
                           (((uint32_t)(ch ^ (row & 7))) << 4),
                       Bp + (size_t)row * DD + k0 + ch * 8);
        }
        CP_COMMIT();
    };

    // Per-lane ldmatrix row assignments (fixed across the k loop)
    const int sel = lane >> 3, ro = lane & 7;
    const int a_row_off = ((sel & 1) << 3) + ro;      // + mt*16 + wm*32
    const int a_cbit    = sel >> 1;
    const int b_row_off = ((sel >> 1) << 3) + ro;     // + ntp*16 + wn*64
    const int b_cbit    = sel & 1;

    float c[2][8][4];
#pragma unroll
    for (int i = 0; i < 2; i++)
#pragma unroll
        for (int j = 0; j < 8; j++)
#pragma unroll
            for (int q = 0; q < 4; q++) c[i][j][q] = 0.0f;

    issue(0); issue(1);

    for (int s = 0; s < NSLAB; s++) {
        CP_WAIT(1);
        __syncthreads();
        if (s + 2 < NSLAB) issue(s + 2);

        const uint32_t As = smb + (s % STAGES) * STAGE_BYTES;
        const uint32_t Bs = As + A_BYTES;
#pragma unroll
        for (int ks = 0; ks < 4; ks++) {              // 4 x K16 = KT 64
            uint32_t af[2][4], bf[8][2];
#pragma unroll
            for (int mt = 0; mt < 2; mt++) {
                const int row = wm * 32 + mt * 16 + a_row_off;
                const int ch  = (2 * ks + a_cbit) ^ (row & 7);
                ldsm4(af[mt][0], af[mt][1], af[mt][2], af[mt][3],
                      As + row * 128 + (ch << 4));
            }
#pragma unroll
            for (int ntp = 0; ntp < 4; ntp++) {
                const int row = wn * 64 + ntp * 16 + b_row_off;
                const int ch  = (2 * ks + b_cbit) ^ (row & 7);
                ldsm4(bf[2 * ntp][0], bf[2 * ntp][1],
                      bf[2 * ntp + 1][0], bf[2 * ntp + 1][1],
                      Bs + row * 128 + (ch << 4));
            }
#pragma unroll
            for (int mt = 0; mt < 2; mt++)
#pragma unroll
                for (int nt = 0; nt < 8; nt++)
                    mma16(c[mt][nt], af[mt], bf[nt][0], bf[nt][1]);
        }
        __syncthreads();
    }

    // Epilogue: c[mt][nt] covers rows (gid, gid+8), cols (2tig, 2tig+1)
#pragma unroll
    for (int mt = 0; mt < 2; mt++) {
        const int r1 = m0 + wm * 32 + mt * 16 + gid;
        const int r2 = r1 + 8;
        float s1 = 1.0f, s2 = 1.0f;
        if (MODE == 1) {
            s1 = rsqrtf(g_sumsq[r1] * (1.0f / DD) + 1e-5f);
            s2 = rsqrtf(g_sumsq[r2] * (1.0f / DD) + 1e-5f);
        }
#pragma unroll
        for (int nt = 0; nt < 8; nt++) {
            const int cg = n0 + wn * 64 + nt * 8 + 2 * tig;
            if (MODE == 0) {
                __half* base = g_proj + (size_t)(cg >> 11) * PLANE + (cg & (DD - 1));
                *reinterpret_cast<__half2*>(base + (size_t)r1 * DD) =
                    __floats2half2_rn(c[mt][nt][0], c[mt][nt][1]);
                *reinterpret_cast<__half2*>(base + (size_t)r2 * DD) =
                    __floats2half2_rn(c[mt][nt][2], c[mt][nt][3]);
            } else {
                *reinterpret_cast<float2*>(out + (size_t)r1 * DD + cg) =
                    make_float2(c[mt][nt][0] * s1, c[mt][nt][1] * s1);
                *reinterpret_cast<float2*>(out + (size_t)r2 * DD + cg) =
                    make_float2(c[mt][nt][2] * s2, c[mt][nt][3] * s2);
            }
        }
    }
}

// ---------------------------------------------------------------------------
// fp32 -> fp16 conversion
// ---------------------------------------------------------------------------
__global__ void __launch_bounds__(256) f2h_kernel(const float* __restrict__ src,
                                                  __half* __restrict__ dst) {
    const size_t i = ((size_t)blockIdx.x * 256 + threadIdx.x) * 8;
    float4 v0 = *reinterpret_cast<const float4*>(src + i);
    float4 v1 = *reinterpret_cast<const float4*>(src + i + 4);
    __half2 h[4];
    h[0] = __floats2half2_rn(v0.x, v0.y);
    h[1] = __floats2half2_rn(v0.z, v0.w);
    h[2] = __floats2half2_rn(v1.x, v1.y);
    h[3] = __floats2half2_rn(v1.z, v1.w);
    *reinterpret_cast<uint4*>(dst + i) = *reinterpret_cast<uint4*>(h);
}

// ---------------------------------------------------------------------------
// Scan: h_t = a_t h_{t-1} + b_t; a = sigmoid(f), b = silu(i)(1-a)
// Each thread owns a pair of adjacent channels (half2 loads -> full 128B
// lines per warp). Timestep-batched loads hide DRAM latency.
// ---------------------------------------------------------------------------
__device__ __forceinline__ float sigmoidf_(float v) {
    return 1.0f / (1.0f + __expf(-v));
}

__global__ void __launch_bounds__(256) scan_chunk_kernel() {
    const int gid = blockIdx.x * 256 + threadIdx.x;   // (b, c, dp)
    const int dp = gid & (DP - 1);
    const int c  = (gid >> 10) & (NCH - 1);
    const int b  = gid >> 15;
    const size_t rb = ((size_t)(b * SS + c * TC)) * DD + dp * 2;
    const __half2* Ip = reinterpret_cast<const __half2*>(g_proj + rb);
    const __half2* Fp = reinterpret_cast<const __half2*>(g_proj + PLANE + rb);
    float A0 = 1.0f, B0 = 0.0f, A1 = 1.0f, B1 = 0.0f;
    for (int t0 = 0; t0 < TC; t0 += 8) {
        __half2 ih[8], fh[8];
#pragma unroll
        for (int j = 0; j < 8; j++) {
            ih[j] = Ip[(size_t)(t0 + j) * DP];
            fh[j] = Fp[(size_t)(t0 + j) * DP];
        }
#pragma unroll
        for (int j = 0; j < 8; j++) {
            const float2 iv = __half22float2(ih[j]);
            const float2 fv = __half22float2(fh[j]);
            const float a0 = sigmoidf_(fv.x), a1 = sigmoidf_(fv.y);
            A0 *= a0; A1 *= a1;
            B0 = fmaf(a0, B0, iv.x * sigmoidf_(iv.x) * (1.0f - a0));
            B1 = fmaf(a1, B1, iv.y * sigmoidf_(iv.y) * (1.0f - a1));
        }
    }
    const int idx = ((b * NCH + c) << 11) + dp * 2;   // (b,c,d) float index
    *reinterpret_cast<float2*>(g_carryA + idx) = make_float2(A0, A1);
    *reinterpret_cast<float2*>(g_carryB + idx) = make_float2(B0, B1);
}

__global__ void __launch_bounds__(256) scan_prefix_kernel() {
    const int id = blockIdx.x * 256 + threadIdx.x;    // (b, dp)
    const int dp = id & (DP - 1);
    const int b  = id >> 10;
    float2 h = make_float2(0.0f, 0.0f);
#pragma unroll
    for (int c = 0; c < NCH; c++) {
        const int idx = ((b * NCH + c) << 11) + dp * 2;
        *reinterpret_cast<float2*>(g_h0 + idx) = h;
        const float2 A = *reinterpret_cast<const float2*>(g_carryA + idx);
        const float2 Bc = *reinterpret_cast<const float2*>(g_carryB + idx);
        h.x = fmaf(A.x, h.x, Bc.x);
        h.y = fmaf(A.y, h.y, Bc.y);
    }
}

__global__ void __launch_bounds__(256) scan_apply_kernel(const float* __restrict__ w_norm) {
    const int gid = blockIdx.x * 256 + threadIdx.x;   // (b, c, dp)
    const int dp = gid & (DP - 1);
    const int c  = (gid >> 10) & (NCH - 1);
    const int b  = gid >> 15;
    const int lane = threadIdx.x & 31;
    const size_t rb = ((size_t)(b * SS + c * TC)) * DD + dp * 2;
    const __half2* Ip = reinterpret_cast<const __half2*>(g_proj + rb);
    const __half2* Fp = reinterpret_cast<const __half2*>(g_proj + PLANE + rb);
    const __half2* Gp = reinterpret_cast<const __half2*>(g_proj + 2 * PLANE + rb);
    __half2* Xp = reinterpret_cast<__half2*>(g_xgh + rb);
    const float2 h0v = *reinterpret_cast<const float2*>(
        g_h0 + ((b * NCH + c) << 11) + dp * 2);
    float h0 = h0v.x, h1 = h0v.y;
    const float2 wn = *reinterpret_cast<const float2*>(w_norm + dp * 2);
    const int prow0 = b * SS + c * TC;
    const int pcol = dp >> 5;                         // warp's channel group
    for (int t0 = 0; t0 < TC; t0 += 4) {
        __half2 ih[4], fh[4], gh[4];
#pragma unroll
        for (int j = 0; j < 4; j++) {
            ih[j] = Ip[(size_t)(t0 + j) * DP];
            fh[j] = Fp[(size_t)(t0 + j) * DP];
            gh[j] = Gp[(size_t)(t0 + j) * DP];
        }
#pragma unroll
        for (int j = 0; j < 4; j++) {
            const float2 iv = __half22float2(ih[j]);
            const float2 fv = __half22float2(fh[j]);
            const float2 gv = __half22float2(gh[j]);
            const float a0 = sigmoidf_(fv.x), a1 = sigmoidf_(fv.y);
            h0 = fmaf(a0, h0, iv.x * sigmoidf_(iv.x) * (1.0f - a0));
            h1 = fmaf(a1, h1, iv.y * sigmoidf_(iv.y) * (1.0f - a1));
            const float xg0 = h0 * (gv.x * sigmoidf_(gv.x));
            const float xg1 = h1 * (gv.y * sigmoidf_(gv.y));
            float ssv = fmaf(xg0, xg0, xg1 * xg1);
#pragma unroll
            for (int o = 16; o; o >>= 1) ssv += __shfl_xor_sync(0xffffffffu, ssv, o);
            if (lane == 0) g_part[(size_t)(prow0 + t0 + j) * 32 + pcol] = ssv;
            Xp[(size_t)(t0 + j) * DP] = __floats2half2_rn(xg0 * wn.x, xg1 * wn.y);
        }
    }
}

__global__ void __launch_bounds__(256) sumsq_reduce_kernel() {
    const int r = blockIdx.x * 256 + threadIdx.x;     // 16384 rows
    const float4* p = reinterpret_cast<const float4*>(g_part + (size_t)r * 32);
    float s = 0.0f;
#pragma unroll
    for (int i = 0; i < 8; i++) {
        float4 v = p[i];
        s += (v.x + v.y) + (v.z + v.w);
    }
    g_sumsq[r] = s;
}

// ---------------------------------------------------------------------------
// Launcher
// ---------------------------------------------------------------------------
extern "C" void kernel_launch(void* const* d_in, const int* in_sizes, int n_in,
                              void* d_out, int out_size) {
    const float* x  = (const float*)d_in[0];
    const float* Wi = (const float*)d_in[1];
    const float* Wf = (const float*)d_in[2];
    const float* Wg = (const float*)d_in[3];
    const float* wn = (const float*)d_in[4];
    const float* Wo = (const float*)d_in[5];
    float* out = (float*)d_out;

    cudaFuncSetAttribute(gemm_f16_kernel<0>,
                         cudaFuncAttributeMaxDynamicSharedMemorySize, SMEM_BYTES);
    cudaFuncSetAttribute(gemm_f16_kernel<1>,
                         cudaFuncAttributeMaxDynamicSharedMemorySize, SMEM_BYTES);

    __half* xh;  cudaGetSymbolAddress((void**)&xh,  g_xh);
    __half* wh;  cudaGetSymbolAddress((void**)&wh,  g_wh);
    __half* woh; cudaGetSymbolAddress((void**)&woh, g_woh);

    // 0) fp32 -> fp16 conversions
    constexpr int WEL = DD * DD;             // 4,194,304
    f2h_kernel<<<PLANE / 2048, 256>>>(x, xh);
    f2h_kernel<<<WEL / 2048, 256>>>(Wi, wh);
    f2h_kernel<<<WEL / 2048, 256>>>(Wf, wh + (size_t)WEL);
    f2h_kernel<<<WEL / 2048, 256>>>(Wg, wh + 2 * (size_t)WEL);
    f2h_kernel<<<WEL / 2048, 256>>>(Wo, woh);

    // 1) Fused projection GEMM over concatenated N = 6144 (i | f | g)
    dim3 g1(RM / MT, 3 * DD / NT);   // (128, 48)
    gemm_f16_kernel<0><<<g1, 256, SMEM_BYTES>>>(nullptr);

    // 2) Chunked linear scan + RMS statistics (channel-paired)
    scan_chunk_kernel<<<(BB * NCH * DP) / 256, 256>>>();
    scan_prefix_kernel<<<(BB * DP) / 256, 256>>>();
    scan_apply_kernel<<<(BB * NCH * DP) / 256, 256>>>(wn);
    sumsq_reduce_kernel<<<RM / 256, 256>>>();

    // 3) Output GEMM with fused RMSNorm row scaling
    dim3 g2(RM / MT, DD / NT);       // (128, 16)
    gemm_f16_kernel<1><<<g2, 256, SMEM_BYTES>>>(out);
}

// round 6
// speedup vs baseline: 2.6376x; 1.0003x over previous
#include <cuda_runtime.h>
#include <cuda_fp16.h>
#include <cstdint>

// ============================================================================
// Problem: x[4, 4096, 2048]; Wi/Wf/Wg/Wo [2048, 2048]; w_norm [2048]; fp32.
// Pipeline: fp32->fp16 convert -> fp16 GEMM(i|f|g, fp16 planes) ->
//           half2 channel-paired chunked linear scan -> gated RMS stats ->
//           fp16 GEMM(out) with fused row-scale epilogue.
// GEMM: m16n8k16 HMMA, tile 128x128x64, 3-stage cp.async, 2 CTAs/SM,
//       N-fastest grid so B (weights) stays L2-resident and A streams once.
// ============================================================================
constexpr int BB = 4;
constexpr int SS = 4096;
constexpr int DD = 2048;
constexpr int RM = BB * SS;                 // 16384 rows
constexpr size_t PLANE = (size_t)RM * DD;   // 33,554,432 elements

constexpr int TC  = 128;                    // scan chunk length
constexpr int NCH = SS / TC;                // 32 chunks
constexpr int DP  = DD / 2;                 // 1024 channel pairs

// ---------------------------------------------------------------------------
// Device scratch (static; allocations are forbidden)
// ---------------------------------------------------------------------------
__device__ __half g_proj[3 * PLANE];        // i, f, g planes (fp16)
__device__ __half g_xh[PLANE];              // x in fp16
__device__ __half g_wh[3 * (size_t)DD * DD];// Wi|Wf|Wg in fp16 (concat rows)
__device__ __half g_woh[(size_t)DD * DD];   // Wo in fp16
__device__ __half g_xgh[PLANE];             // xg * w_norm in fp16 (GEMM2 A)
__device__ float  g_carryA[BB * NCH * DD];
__device__ float  g_carryB[BB * NCH * DD];
__device__ float  g_h0[BB * NCH * DD];
__device__ float  g_part[(size_t)RM * 32];  // per-row per-warp sumsq partials
__device__ float  g_sumsq[RM];

// ---------------------------------------------------------------------------
// PTX helpers (sm_80-era only — safe under virtual arch compute_103)
// ---------------------------------------------------------------------------
__device__ __forceinline__ uint32_t smem_u32(const void* p) {
    uint32_t a;
    asm("{ .reg .u64 t; cvta.to.shared.u64 t, %1; cvt.u32.u64 %0, t; }"
        : "=r"(a) : "l"(p));
    return a;
}

#define CP_ASYNC16(dst, src) \
    asm volatile("cp.async.cg.shared.global [%0], [%1], 16;" \
                 :: "r"(dst), "l"(src))
#define CP_COMMIT() asm volatile("cp.async.commit_group;" ::: "memory")
#define CP_WAIT(n)  asm volatile("cp.async.wait_group %0;" :: "n"(n) : "memory")

__device__ __forceinline__ void ldsm4(uint32_t& r0, uint32_t& r1,
                                      uint32_t& r2, uint32_t& r3, uint32_t a) {
    asm volatile("ldmatrix.sync.aligned.m8n8.x4.shared.b16 {%0,%1,%2,%3}, [%4];"
                 : "=r"(r0), "=r"(r1), "=r"(r2), "=r"(r3) : "r"(a));
}

// D(16x8) += A(16x16) * B(16x8), fp16 inputs, fp32 accumulate.
__device__ __forceinline__ void mma16(float* c, const uint32_t* a,
                                      uint32_t b0, uint32_t b1) {
    asm volatile(
        "mma.sync.aligned.m16n8k16.row.col.f32.f16.f16.f32 "
        "{%0,%1,%2,%3}, {%4,%5,%6,%7}, {%8,%9}, {%0,%1,%2,%3};"
        : "+f"(c[0]), "+f"(c[1]), "+f"(c[2]), "+f"(c[3])
        : "r"(a[0]), "r"(a[1]), "r"(a[2]), "r"(a[3]), "r"(b0), "r"(b1));
}

// ---------------------------------------------------------------------------
// fp16 GEMM: C[m,n] = sum_k A[m,k]*B[n,k], A,B row-major fp16.
// CTA tile 128x128x64, 256 threads, 8 warps of 32x64, 3-stage cp.async,
// 2 CTAs/SM. Grid: x = N tiles (fastest) -> B is L2-resident, A streams once.
// MODE 0: A=g_xh, B=g_wh (i|f|g concat); writes fp16 i/f/g planes.
// MODE 1: A=g_xgh, B=g_woh; epilogue scales each row by rsqrt(mean sumsq+eps).
// ---------------------------------------------------------------------------
constexpr int MT = 128, NT = 128, KT = 64;
constexpr int NSLAB  = DD / KT;             // 32
constexpr int STAGES = 3;
constexpr int A_BYTES = MT * KT * 2;        // 16 KB (rows of 128 B)
constexpr int B_BYTES = NT * KT * 2;        // 16 KB
constexpr int STAGE_BYTES = A_BYTES + B_BYTES;       // 32 KB
constexpr int SMEM_BYTES  = STAGES * STAGE_BYTES;    // 96 KB

// smem: row m = 64 halves (128 B) as 8 16-byte chunks; chunk ch of row m at
// byte m*128 + ((ch ^ (m&7)) << 4). Conflict-free for cp.async stores and
// for ldmatrix reads.

template <int MODE>
__global__ void __launch_bounds__(256, 2) gemm_f16_kernel(float* __restrict__ out) {
    extern __shared__ char sm[];
    const uint32_t smb = smem_u32(sm);
    const int tid  = threadIdx.x;
    const int lane = tid & 31, gid = lane >> 2, tig = lane & 3;
    const int wid  = tid >> 5, wm = wid & 3, wn = wid >> 2;

    const int n0 = blockIdx.x * NT;     // N fastest
    const int m0 = blockIdx.y * MT;

    const __half* Ap = (MODE == 0 ? g_xh : g_xgh) + (size_t)m0 * DD;
    const __half* Bp = (MODE == 0 ? g_wh : g_woh) + (size_t)n0 * DD;

    auto issue = [&](int s) {
        const int k0 = s * KT;
        const uint32_t sb = smb + (uint32_t)((s % STAGES) * STAGE_BYTES);
#pragma unroll
        for (int i = 0; i < 4; i++) {                 // A: 128 rows x 8 chunks
            const int idx = tid + i * 256;
            const int row = idx >> 3, ch = idx & 7;
            CP_ASYNC16(sb + row * 128 + (((uint32_t)(ch ^ (row & 7))) << 4),
                       Ap + (size_t)row * DD + k0 + ch * 8);
        }
#pragma unroll
        for (int i = 0; i < 4; i++) {                 // B: 128 rows x 8 chunks
            const int idx = tid + i * 256;
            const int row = idx >> 3, ch = idx & 7;
            CP_ASYNC16(sb + A_BYTES + row * 128 +
                           (((uint32_t)(ch ^ (row & 7))) << 4),
                       Bp + (size_t)row * DD + k0 + ch * 8);
        }
        CP_COMMIT();
    };

    // Per-lane ldmatrix row assignments (fixed across the k loop)
    const int sel = lane >> 3, ro = lane & 7;
    const int a_row_off = ((sel & 1) << 3) + ro;      // + mt*16 + wm*32
    const int a_cbit    = sel >> 1;
    const int b_row_off = ((sel >> 1) << 3) + ro;     // + ntp*16 + wn*64
    const int b_cbit    = sel & 1;

    float c[2][8][4];
#pragma unroll
    for (int i = 0; i < 2; i++)
#pragma unroll
        for (int j = 0; j < 8; j++)
#pragma unroll
            for (int q = 0; q < 4; q++) c[i][j][q] = 0.0f;

    issue(0); issue(1);

    for (int s = 0; s < NSLAB; s++) {
        CP_WAIT(1);
        __syncthreads();   // all CTA's copies for stage s visible; all warps
                           // past stage s-3's reads -> safe to refill it
        if (s + 2 < NSLAB) issue(s + 2);

        const uint32_t As = smb + (s % STAGES) * STAGE_BYTES;
        const uint32_t Bs = As + A_BYTES;
#pragma unroll
        for (int ks = 0; ks < 4; ks++) {              // 4 x K16 = KT 64
            uint32_t af[2][4], bf[8][2];
#pragma unroll
            for (int mt = 0; mt < 2; mt++) {
                const int row = wm * 32 + mt * 16 + a_row_off;
                const int ch  = (2 * ks + a_cbit) ^ (row & 7);
                ldsm4(af[mt][0], af[mt][1], af[mt][2], af[mt][3],
                      As + row * 128 + (ch << 4));
            }
#pragma unroll
            for (int ntp = 0; ntp < 4; ntp++) {
                const int row = wn * 64 + ntp * 16 + b_row_off;
                const int ch  = (2 * ks + b_cbit) ^ (row & 7);
                ldsm4(bf[2 * ntp][0], bf[2 * ntp][1],
                      bf[2 * ntp + 1][0], bf[2 * ntp + 1][1],
                      Bs + row * 128 + (ch << 4));
            }
#pragma unroll
            for (int mt = 0; mt < 2; mt++)
#pragma unroll
                for (int nt = 0; nt < 8; nt++)
                    mma16(c[mt][nt], af[mt], bf[nt][0], bf[nt][1]);
        }
    }

    // Epilogue: c[mt][nt] covers rows (gid, gid+8), cols (2tig, 2tig+1)
#pragma unroll
    for (int mt = 0; mt < 2; mt++) {
        const int r1 = m0 + wm * 32 + mt * 16 + gid;
        const int r2 = r1 + 8;
        float s1 = 1.0f, s2 = 1.0f;
        if (MODE == 1) {
            s1 = rsqrtf(g_sumsq[r1] * (1.0f / DD) + 1e-5f);
            s2 = rsqrtf(g_sumsq[r2] * (1.0f / DD) + 1e-5f);
        }
#pragma unroll
        for (int nt = 0; nt < 8; nt++) {
            const int cg = n0 + wn * 64 + nt * 8 + 2 * tig;
            if (MODE == 0) {
                __half* base = g_proj + (size_t)(cg >> 11) * PLANE + (cg & (DD - 1));
                *reinterpret_cast<__half2*>(base + (size_t)r1 * DD) =
                    __floats2half2_rn(c[mt][nt][0], c[mt][nt][1]);
                *reinterpret_cast<__half2*>(base + (size_t)r2 * DD) =
                    __floats2half2_rn(c[mt][nt][2], c[mt][nt][3]);
            } else {
                *reinterpret_cast<float2*>(out + (size_t)r1 * DD + cg) =
                    make_float2(c[mt][nt][0] * s1, c[mt][nt][1] * s1);
                *reinterpret_cast<float2*>(out + (size_t)r2 * DD + cg) =
                    make_float2(c[mt][nt][2] * s2, c[mt][nt][3] * s2);
            }
        }
    }
}

// ---------------------------------------------------------------------------
// fp32 -> fp16 conversion: 16 elements/thread, 4 independent float4 loads
// ---------------------------------------------------------------------------
__device__ __forceinline__ void cvt16(const float* __restrict__ src,
                                      __half* __restrict__ dst, size_t i) {
    float4 v[4];
#pragma unroll
    for (int j = 0; j < 4; j++)
        v[j] = *reinterpret_cast<const float4*>(src + i + j * 4);
#pragma unroll
    for (int j = 0; j < 4; j++) {
        __half2 h[2];
        h[0] = __floats2half2_rn(v[j].x, v[j].y);
        h[1] = __floats2half2_rn(v[j].z, v[j].w);
        *reinterpret_cast<uint2*>(dst + i + j * 4) = *reinterpret_cast<uint2*>(h);
    }
}

__global__ void __launch_bounds__(256) f2h_x_kernel(const float* __restrict__ src,
                                                    __half* __restrict__ dst) {
    cvt16(src, dst, ((size_t)blockIdx.x * 256 + threadIdx.x) * 16);
}

// One launch for all four weight matrices: blockIdx.y selects the matrix.
__global__ void __launch_bounds__(256) f2h_w_kernel(
    const float* __restrict__ w0, const float* __restrict__ w1,
    const float* __restrict__ w2, const float* __restrict__ w3) {
    const size_t i = ((size_t)blockIdx.x * 256 + threadIdx.x) * 16;
    const int m = blockIdx.y;
    const float* src = (m == 0) ? w0 : (m == 1) ? w1 : (m == 2) ? w2 : w3;
    __half* dst = (m < 3) ? (g_wh + (size_t)m * DD * DD) : g_woh;
    cvt16(src, dst, i);
}

// ---------------------------------------------------------------------------
// Scan: h_t = a_t h_{t-1} + b_t; a = sigmoid(f), b = silu(i)(1-a)
// Each thread owns a pair of adjacent channels (half2 loads -> full 128B
// lines per warp). Timestep-batched loads (x8) hide DRAM latency.
// ---------------------------------------------------------------------------
__device__ __forceinline__ float sigmoidf_(float v) {
    return 1.0f / (1.0f + __expf(-v));
}

__global__ void __launch_bounds__(256) scan_chunk_kernel() {
    const int gid = blockIdx.x * 256 + threadIdx.x;   // (b, c, dp)
    const int dp = gid & (DP - 1);
    const int c  = (gid >> 10) & (NCH - 1);
    const int b  = gid >> 15;
    const size_t rb = ((size_t)(b * SS + c * TC)) * DD + dp * 2;
    const __half2* Ip = reinterpret_cast<const __half2*>(g_proj + rb);
    const __half2* Fp = reinterpret_cast<const __half2*>(g_proj + PLANE + rb);
    float A0 = 1.0f, B0 = 0.0f, A1 = 1.0f, B1 = 0.0f;
    for (int t0 = 0; t0 < TC; t0 += 8) {
        __half2 ih[8], fh[8];
#pragma unroll
        for (int j = 0; j < 8; j++) {
            ih[j] = Ip[(size_t)(t0 + j) * DP];
            fh[j] = Fp[(size_t)(t0 + j) * DP];
        }
#pragma unroll
        for (int j = 0; j < 8; j++) {
            const float2 iv = __half22float2(ih[j]);
            const float2 fv = __half22float2(fh[j]);
            const float a0 = sigmoidf_(fv.x), a1 = sigmoidf_(fv.y);
            A0 *= a0; A1 *= a1;
            B0 = fmaf(a0, B0, iv.x * sigmoidf_(iv.x) * (1.0f - a0));
            B1 = fmaf(a1, B1, iv.y * sigmoidf_(iv.y) * (1.0f - a1));
        }
    }
    const int idx = ((b * NCH + c) << 11) + dp * 2;   // (b,c,d) float index
    *reinterpret_cast<float2*>(g_carryA + idx) = make_float2(A0, A1);
    *reinterpret_cast<float2*>(g_carryB + idx) = make_float2(B0, B1);
}

__global__ void __launch_bounds__(256) scan_prefix_kernel() {
    const int id = blockIdx.x * 256 + threadIdx.x;    // (b, dp)
    const int dp = id & (DP - 1);
    const int b  = id >> 10;
    float2 h = make_float2(0.0f, 0.0f);
#pragma unroll
    for (int c = 0; c < NCH; c++) {
        const int idx = ((b * NCH + c) << 11) + dp * 2;
        *reinterpret_cast<float2*>(g_h0 + idx) = h;
        const float2 A = *reinterpret_cast<const float2*>(g_carryA + idx);
        const float2 Bc = *reinterpret_cast<const float2*>(g_carryB + idx);
        h.x = fmaf(A.x, h.x, Bc.x);
        h.y = fmaf(A.y, h.y, Bc.y);
    }
}

__global__ void __launch_bounds__(256) scan_apply_kernel(const float* __restrict__ w_norm) {
    const int gid = blockIdx.x * 256 + threadIdx.x;   // (b, c, dp)
    const int dp = gid & (DP - 1);
    const int c  = (gid >> 10) & (NCH - 1);
    const int b  = gid >> 15;
    const int lane = threadIdx.x & 31;
    const size_t rb = ((size_t)(b * SS + c * TC)) * DD + dp * 2;
    const __half2* Ip = reinterpret_cast<const __half2*>(g_proj + rb);
    const __half2* Fp = reinterpret_cast<const __half2*>(g_proj + PLANE + rb);
    const __half2* Gp = reinterpret_cast<const __half2*>(g_proj + 2 * PLANE + rb);
    __half2* Xp = reinterpret_cast<__half2*>(g_xgh + rb);
    const float2 h0v = *reinterpret_cast<const float2*>(
        g_h0 + ((b * NCH + c) << 11) + dp * 2);
    float h0 = h0v.x, h1 = h0v.y;
    const float2 wn = *reinterpret_cast<const float2*>(w_norm + dp * 2);
    const int prow0 = b * SS + c * TC;
    const int pcol = dp >> 5;                         // warp's channel group
    for (int t0 = 0; t0 < TC; t0 += 8) {
        __half2 ih[8], fh[8], gh[8];
#pragma unroll
        for (int j = 0; j < 8; j++) {
            ih[j] = Ip[(size_t)(t0 + j) * DP];
            fh[j] = Fp[(size_t)(t0 + j) * DP];
            gh[j] = Gp[(size_t)(t0 + j) * DP];
        }
#pragma unroll
        for (int j = 0; j < 8; j++) {
            const float2 iv = __half22float2(ih[j]);
            const float2 fv = __half22float2(fh[j]);
            const float2 gv = __half22float2(gh[j]);
            const float a0 = sigmoidf_(fv.x), a1 = sigmoidf_(fv.y);
            h0 = fmaf(a0, h0, iv.x * sigmoidf_(iv.x) * (1.0f - a0));
            h1 = fmaf(a1, h1, iv.y * sigmoidf_(iv.y) * (1.0f - a1));
            const float xg0 = h0 * (gv.x * sigmoidf_(gv.x));
            const float xg1 = h1 * (gv.y * sigmoidf_(gv.y));
            float ssv = fmaf(xg0, xg0, xg1 * xg1);
#pragma unroll
            for (int o = 16; o; o >>= 1) ssv += __shfl_xor_sync(0xffffffffu, ssv, o);
            if (lane == 0) g_part[(size_t)(prow0 + t0 + j) * 32 + pcol] = ssv;
            Xp[(size_t)(t0 + j) * DP] = __floats2half2_rn(xg0 * wn.x, xg1 * wn.y);
        }
    }
}

__global__ void __launch_bounds__(256) sumsq_reduce_kernel() {
    const int r = blockIdx.x * 256 + threadIdx.x;     // 16384 rows
    const float4* p = reinterpret_cast<const float4*>(g_part + (size_t)r * 32);
    float s = 0.0f;
#pragma unroll
    for (int i = 0; i < 8; i++) {
        float4 v = p[i];
        s += (v.x + v.y) + (v.z + v.w);
    }
    g_sumsq[r] = s;
}

// ---------------------------------------------------------------------------
// Launcher
// ---------------------------------------------------------------------------
extern "C" void kernel_launch(void* const* d_in, const int* in_sizes, int n_in,
                              void* d_out, int out_size) {
    const float* x  = (const float*)d_in[0];
    const float* Wi = (const float*)d_in[1];
    const float* Wf = (const float*)d_in[2];
    const float* Wg = (const float*)d_in[3];
    const float* wn = (const float*)d_in[4];
    const float* Wo = (const float*)d_in[5];
    float* out = (float*)d_out;

    cudaFuncSetAttribute(gemm_f16_kernel<0>,
                         cudaFuncAttributeMaxDynamicSharedMemorySize, SMEM_BYTES);
    cudaFuncSetAttribute(gemm_f16_kernel<1>,
                         cudaFuncAttributeMaxDynamicSharedMemorySize, SMEM_BYTES);

    __half* xh;  cudaGetSymbolAddress((void**)&xh, g_xh);

    // 0) fp32 -> fp16 conversions (x: 8192 blocks; weights: one 2-D launch)
    constexpr int WEL = DD * DD;             // 4,194,304
    f2h_x_kernel<<<PLANE / 4096, 256>>>(x, xh);
    f2h_w_kernel<<<dim3(WEL / 4096, 4), 256>>>(Wi, Wf, Wg, Wo);

    // 1) Fused projection GEMM over concatenated N = 6144 (i | f | g)
    dim3 g1(3 * DD / NT, RM / MT);   // (48, 128), N fastest
    gemm_f16_kernel<0><<<g1, 256, SMEM_BYTES>>>(nullptr);

    // 2) Chunked linear scan + RMS statistics (channel-paired)
    scan_chunk_kernel<<<(BB * NCH * DP) / 256, 256>>>();
    scan_prefix_kernel<<<(BB * DP) / 256, 256>>>();
    scan_apply_kernel<<<(BB * NCH * DP) / 256, 256>>>(wn);
    sumsq_reduce_kernel<<<RM / 256, 256>>>();

    // 3) Output GEMM with fused RMSNorm row scaling
    dim3 g2(DD / NT, RM / MT);       // (16, 128), N fastest
    gemm_f16_kernel<1><<<g2, 256, SMEM_BYTES>>>(out);
}

// round 8
// speedup vs baseline: 2.6988x; 1.0232x over previous
#include <cuda_runtime.h>
#include <cuda_fp16.h>
#include <cstdint>

// ============================================================================
// Problem: x[4, 4096, 2048]; Wi/Wf/Wg/Wo [2048, 2048]; w_norm [2048]; fp32.
// Pipeline: fp32->fp16 convert -> fp16 GEMM(i|f|g) with gate transforms fused
//           into the epilogue (stores si=silu(i), a=sigmoid(f), sg=silu(g)) ->
//           pure-FMA chunked linear scan -> gated RMS stats ->
//           fp16 GEMM(out) with fused row-scale epilogue.
// GEMM: m16n8k16 HMMA, tile 128x128x64, 3-stage cp.async, 2 CTAs/SM.
// ============================================================================
constexpr int BB = 4;
constexpr int SS = 4096;
constexpr int DD = 2048;
constexpr int RM = BB * SS;                 // 16384 rows
constexpr size_t PLANE = (size_t)RM * DD;   // 33,554,432 elements

constexpr int TC  = 64;                     // scan chunk length
constexpr int NCH = SS / TC;                // 64 chunks
constexpr int DP  = DD / 2;                 // 1024 channel pairs

// ---------------------------------------------------------------------------
// Device scratch (static; allocations are forbidden)
// ---------------------------------------------------------------------------
__device__ __half g_proj[3 * PLANE];        // si, a, sg planes (fp16)
__device__ __half g_xh[PLANE];              // x in fp16
__device__ __half g_wh[3 * (size_t)DD * DD];// Wi|Wf|Wg in fp16 (concat rows)
__device__ __half g_woh[(size_t)DD * DD];   // Wo in fp16
__device__ __half g_xgh[PLANE];             // xg * w_norm in fp16 (GEMM2 A)
__device__ float  g_carryA[BB * NCH * DD];
__device__ float  g_carryB[BB * NCH * DD];
__device__ float  g_h0[BB * NCH * DD];
__device__ float  g_part[(size_t)RM * 32];  // per-row per-warp sumsq partials
__device__ float  g_sumsq[RM];

// ---------------------------------------------------------------------------
// PTX helpers (sm_80-era only — safe under virtual arch compute_103)
// ---------------------------------------------------------------------------
__device__ __forceinline__ uint32_t smem_u32(const void* p) {
    uint32_t a;
    asm("{ .reg .u64 t; cvta.to.shared.u64 t, %1; cvt.u32.u64 %0, t; }"
        : "=r"(a) : "l"(p));
    return a;
}

#define CP_ASYNC16(dst, src) \
    asm volatile("cp.async.cg.shared.global [%0], [%1], 16;" \
                 :: "r"(dst), "l"(src))
#define CP_COMMIT() asm volatile("cp.async.commit_group;" ::: "memory")
#define CP_WAIT(n)  asm volatile("cp.async.wait_group %0;" :: "n"(n) : "memory")

__device__ __forceinline__ void ldsm4(uint32_t& r0, uint32_t& r1,
                                      uint32_t& r2, uint32_t& r3, uint32_t a) {
    asm volatile("ldmatrix.sync.aligned.m8n8.x4.shared.b16 {%0,%1,%2,%3}, [%4];"
                 : "=r"(r0), "=r"(r1), "=r"(r2), "=r"(r3) : "r"(a));
}

// D(16x8) += A(16x16) * B(16x8), fp16 inputs, fp32 accumulate.
__device__ __forceinline__ void mma16(float* c, const uint32_t* a,
                                      uint32_t b0, uint32_t b1) {
    asm volatile(
        "mma.sync.aligned.m16n8k16.row.col.f32.f16.f16.f32 "
        "{%0,%1,%2,%3}, {%4,%5,%6,%7}, {%8,%9}, {%0,%1,%2,%3};"
        : "+f"(c[0]), "+f"(c[1]), "+f"(c[2]), "+f"(c[3])
        : "r"(a[0]), "r"(a[1]), "r"(a[2]), "r"(a[3]), "r"(b0), "r"(b1));
}

__device__ __forceinline__ float sigmoidf_(float v) {
    return 1.0f / (1.0f + __expf(-v));
}

// ---------------------------------------------------------------------------
// fp16 GEMM: C[m,n] = sum_k A[m,k]*B[n,k], A,B row-major fp16.
// CTA tile 128x128x64, 256 threads, 8 warps of 32x64, 3-stage cp.async,
// 2 CTAs/SM (one CTA's sync/epilogue overlaps the other's MMAs).
// MODE 0: A=g_xh, B=g_wh (i|f|g concat); epilogue applies the gate
//         activation per plane (MUFU hidden under the tensor pipe) and
//         stores si / a / sg in fp16.
// MODE 1: A=g_xgh, B=g_woh; epilogue scales each row by rsqrt(mean sumsq+eps).
// ---------------------------------------------------------------------------
constexpr int MT = 128, NT = 128, KT = 64;
constexpr int NSLAB  = DD / KT;             // 32
constexpr int STAGES = 3;
constexpr int A_BYTES = MT * KT * 2;        // 16 KB (rows of 128 B)
constexpr int B_BYTES = NT * KT * 2;        // 16 KB
constexpr int STAGE_BYTES = A_BYTES + B_BYTES;       // 32 KB
constexpr int SMEM_BYTES  = STAGES * STAGE_BYTES;    // 96 KB

template <int MODE>
__global__ void __launch_bounds__(256, 2) gemm_f16_kernel(float* __restrict__ out) {
    extern __shared__ char sm[];
    const uint32_t smb = smem_u32(sm);
    const int tid  = threadIdx.x;
    const int lane = tid & 31, gid = lane >> 2, tig = lane & 3;
    const int wid  = tid >> 5, wm = wid & 3, wn = wid >> 2;

    const int n0 = blockIdx.x * NT;     // N fastest
    const int m0 = blockIdx.y * MT;

    const __half* Ap = (MODE == 0 ? g_xh : g_xgh) + (size_t)m0 * DD;
    const __half* Bp = (MODE == 0 ? g_wh : g_woh) + (size_t)n0 * DD;

    auto issue = [&](int s) {
        const int k0 = s * KT;
        const uint32_t sb = smb + (uint32_t)((s % STAGES) * STAGE_BYTES);
#pragma unroll
        for (int i = 0; i < 4; i++) {                 // A: 128 rows x 8 chunks
            const int idx = tid + i * 256;
            const int row = idx >> 3, ch = idx & 7;
            CP_ASYNC16(sb + row * 128 + (((uint32_t)(ch ^ (row & 7))) << 4),
                       Ap + (size_t)row * DD + k0 + ch * 8);
        }
#pragma unroll
        for (int i = 0; i < 4; i++) {                 // B: 128 rows x 8 chunks
            const int idx = tid + i * 256;
            const int row = idx >> 3, ch = idx & 7;
            CP_ASYNC16(sb + A_BYTES + row * 128 +
                           (((uint32_t)(ch ^ (row & 7))) << 4),
                       Bp + (size_t)row * DD + k0 + ch * 8);
        }
        CP_COMMIT();
    };

    // Per-lane ldmatrix row assignments (fixed across the k loop)
    const int sel = lane >> 3, ro = lane & 7;
    const int a_row_off = ((sel & 1) << 3) + ro;      // + mt*16 + wm*32
    const int a_cbit    = sel >> 1;
    const int b_row_off = ((sel >> 1) << 3) + ro;     // + ntp*16 + wn*64
    const int b_cbit    = sel & 1;

    float c[2][8][4];
#pragma unroll
    for (int i = 0; i < 2; i++)
#pragma unroll
        for (int j = 0; j < 8; j++)
#pragma unroll
            for (int q = 0; q < 4; q++) c[i][j][q] = 0.0f;

    issue(0); issue(1);

    for (int s = 0; s < NSLAB; s++) {
        CP_WAIT(1);
        __syncthreads();
        if (s + 2 < NSLAB) issue(s + 2);

        const uint32_t As = smb + (s % STAGES) * STAGE_BYTES;
        const uint32_t Bs = As + A_BYTES;
#pragma unroll
        for (int ks = 0; ks < 4; ks++) {              // 4 x K16 = KT 64
            uint32_t af[2][4], bf[8][2];
#pragma unroll
            for (int mt = 0; mt < 2; mt++) {
                const int row = wm * 32 + mt * 16 + a_row_off;
                const int ch  = (2 * ks + a_cbit) ^ (row & 7);
                ldsm4(af[mt][0], af[mt][1], af[mt][2], af[mt][3],
                      As + row * 128 + (ch << 4));
            }
#pragma unroll
            for (int ntp = 0; ntp < 4; ntp++) {
                const int row = wn * 64 + ntp * 16 + b_row_off;
                const int ch  = (2 * ks + b_cbit) ^ (row & 7);
                ldsm4(bf[2 * ntp][0], bf[2 * ntp][1],
                      bf[2 * ntp + 1][0], bf[2 * ntp + 1][1],
                      Bs + row * 128 + (ch << 4));
            }
#pragma unroll
            for (int mt = 0; mt < 2; mt++)
#pragma unroll
                for (int nt = 0; nt < 8; nt++)
                    mma16(c[mt][nt], af[mt], bf[nt][0], bf[nt][1]);
        }
    }

    // Epilogue: c[mt][nt] covers rows (gid, gid+8), cols (2tig, 2tig+1)
#pragma unroll
    for (int mt = 0; mt < 2; mt++) {
        const int r1 = m0 + wm * 32 + mt * 16 + gid;
        const int r2 = r1 + 8;
        float s1 = 1.0f, s2 = 1.0f;
        if (MODE == 1) {
            s1 = rsqrtf(g_sumsq[r1] * (1.0f / DD) + 1e-5f);
            s2 = rsqrtf(g_sumsq[r2] * (1.0f / DD) + 1e-5f);
        }
#pragma unroll
        for (int nt = 0; nt < 8; nt++) {
            const int cg = n0 + wn * 64 + nt * 8 + 2 * tig;
            if (MODE == 0) {
                const int ws = cg >> 11;              // 0:i  1:f  2:g
                float v[4];
#pragma unroll
                for (int q = 0; q < 4; q++) {
                    const float raw = c[mt][nt][q];
                    const float sg  = sigmoidf_(raw);
                    v[q] = (ws == 1) ? sg : raw * sg; // a  or  silu
                }
                __half* base = g_proj + (size_t)ws * PLANE + (cg & (DD - 1));
                *reinterpret_cast<__half2*>(base + (size_t)r1 * DD) =
                    __floats2half2_rn(v[0], v[1]);
                *reinterpret_cast<__half2*>(base + (size_t)r2 * DD) =
                    __floats2half2_rn(v[2], v[3]);
            } else {
                *reinterpret_cast<float2*>(out + (size_t)r1 * DD + cg) =
                    make_float2(c[mt][nt][0] * s1, c[mt][nt][1] * s1);
                *reinterpret_cast<float2*>(out + (size_t)r2 * DD + cg) =
                    make_float2(c[mt][nt][2] * s2, c[mt][nt][3] * s2);
            }
        }
    }
}

// ---------------------------------------------------------------------------
// fp32 -> fp16 conversion: 16 elements/thread, 4 independent float4 loads
// ---------------------------------------------------------------------------
__device__ __forceinline__ void cvt16(const float* __restrict__ src,
                                      __half* __restrict__ dst, size_t i) {
    float4 v[4];
#pragma unroll
    for (int j = 0; j < 4; j++)
        v[j] = *reinterpret_cast<const float4*>(src + i + j * 4);
#pragma unroll
    for (int j = 0; j < 4; j++) {
        __half2 h[2];
        h[0] = __floats2half2_rn(v[j].x, v[j].y);
        h[1] = __floats2half2_rn(v[j].z, v[j].w);
        *reinterpret_cast<uint2*>(dst + i + j * 4) = *reinterpret_cast<uint2*>(h);
    }
}

__global__ void __launch_bounds__(256) f2h_x_kernel(const float* __restrict__ src,
                                                    __half* __restrict__ dst) {
    cvt16(src, dst, ((size_t)blockIdx.x * 256 + threadIdx.x) * 16);
}

__global__ void __launch_bounds__(256) f2h_w_kernel(
    const float* __restrict__ w0, const float* __restrict__ w1,
    const float* __restrict__ w2, const float* __restrict__ w3) {
    const size_t i = ((size_t)blockIdx.x * 256 + threadIdx.x) * 16;
    const int m = blockIdx.y;
    const float* src = (m == 0) ? w0 : (m == 1) ? w1 : (m == 2) ? w2 : w3;
    __half* dst = (m < 3) ? (g_wh + (size_t)m * DD * DD) : g_woh;
    cvt16(src, dst, i);
}

// ---------------------------------------------------------------------------
// Scan: h_t = a_t h_{t-1} + b_t with b = si*(1-a); planes hold si / a / sg.
// Pure FMA + loads (activations were applied in the GEMM1 epilogue).
// Each thread owns a pair of adjacent channels (half2 loads).
// ---------------------------------------------------------------------------
__global__ void __launch_bounds__(256) scan_chunk_kernel() {
    const int gid = blockIdx.x * 256 + threadIdx.x;   // (b, c, dp)
    const int dp = gid & (DP - 1);
    const int c  = (gid >> 10) & (NCH - 1);
    const int b  = gid >> 16;                         // 10 + 6
    const size_t rb = ((size_t)(b * SS + c * TC)) * DD + dp * 2;
    const __half2* Sp = reinterpret_cast<const __half2*>(g_proj + rb);
    const __half2* Ap = reinterpret_cast<const __half2*>(g_proj + PLANE + rb);
    float A0 = 1.0f, B0 = 0.0f, A1 = 1.0f, B1 = 0.0f;
    for (int t0 = 0; t0 < TC; t0 += 8) {
        __half2 sh[8], ah[8];
#pragma unroll
        for (int j = 0; j < 8; j++) {
            sh[j] = Sp[(size_t)(t0 + j) * DP];
            ah[j] = Ap[(size_t)(t0 + j) * DP];
        }
#pragma unroll
        for (int j = 0; j < 8; j++) {
            const float2 si = __half22float2(sh[j]);
            const float2 av = __half22float2(ah[j]);
            A0 *= av.x; A1 *= av.y;
            B0 = fmaf(av.x, B0, si.x * (1.0f - av.x));
            B1 = fmaf(av.y, B1, si.y * (1.0f - av.y));
        }
    }
    const int idx = ((b * NCH + c) << 11) + dp * 2;   // (b,c,d) float index
    *reinterpret_cast<float2*>(g_carryA + idx) = make_float2(A0, A1);
    *reinterpret_cast<float2*>(g_carryB + idx) = make_float2(B0, B1);
}

__global__ void __launch_bounds__(256) scan_prefix_kernel() {
    const int id = blockIdx.x * 256 + threadIdx.x;    // (b, dp)
    const int dp = id & (DP - 1);
    const int b  = id >> 10;
    float2 h = make_float2(0.0f, 0.0f);
#pragma unroll
    for (int c = 0; c < NCH; c++) {
        const int idx = ((b * NCH + c) << 11) + dp * 2;
        *reinterpret_cast<float2*>(g_h0 + idx) = h;
        const float2 A = *reinterpret_cast<const float2*>(g_carryA + idx);
        const float2 Bc = *reinterpret_cast<const float2*>(g_carryB + idx);
        h.x = fmaf(A.x, h.x, Bc.x);
        h.y = fmaf(A.y, h.y, Bc.y);
    }
}

__global__ void __launch_bounds__(256) scan_apply_kernel(const float* __restrict__ w_norm) {
    const int gid = blockIdx.x * 256 + threadIdx.x;   // (b, c, dp)
    const int dp = gid & (DP - 1);
    const int c  = (gid >> 10) & (NCH - 1);
    const int b  = gid >> 16;
    const int lane = threadIdx.x & 31;
    const size_t rb = ((size_t)(b * SS + c * TC)) * DD + dp * 2;
    const __half2* Sp = reinterpret_cast<const __half2*>(g_proj + rb);
    const __half2* Ap = reinterpret_cast<const __half2*>(g_proj + PLANE + rb);
    const __half2* Gp = reinterpret_cast<const __half2*>(g_proj + 2 * PLANE + rb);
    __half2* Xp = reinterpret_cast<__half2*>(g_xgh + rb);
    const float2 h0v = *reinterpret_cast<const float2*>(
        g_h0 + ((b * NCH + c) << 11) + dp * 2);
    float h0 = h0v.x, h1 = h0v.y;
    const float2 wn = *reinterpret_cast<const float2*>(w_norm + dp * 2);
    const int prow0 = b * SS + c * TC;
    const int pcol = dp >> 5;                         // warp's channel group
    for (int t0 = 0; t0 < TC; t0 += 8) {
        __half2 sh[8], ah[8], gh[8];
#pragma unroll
        for (int j = 0; j < 8; j++) {
            sh[j] = Sp[(size_t)(t0 + j) * DP];
            ah[j] = Ap[(size_t)(t0 + j) * DP];
            gh[j] = Gp[(size_t)(t0 + j) * DP];
        }
#pragma unroll
        for (int j = 0; j < 8; j++) {
            const float2 si = __half22float2(sh[j]);
            const float2 av = __half22float2(ah[j]);
            const float2 sg = __half22float2(gh[j]);
            h0 = fmaf(av.x, h0, si.x * (1.0f - av.x));
            h1 = fmaf(av.y, h1, si.y * (1.0f - av.y));
            const float xg0 = h0 * sg.x;
            const float xg1 = h1 * sg.y;
            float ssv = fmaf(xg0, xg0, xg1 * xg1);
#pragma unroll
            for (int o = 16; o; o >>= 1) ssv += __shfl_xor_sync(0xffffffffu, ssv, o);
            if (lane == 0) g_part[(size_t)(prow0 + t0 + j) * 32 + pcol] = ssv;
            Xp[(size_t)(t0 + j) * DP] = __floats2half2_rn(xg0 * wn.x, xg1 * wn.y);
        }
    }
}

__global__ void __launch_bounds__(256) sumsq_reduce_kernel() {
    const int r = blockIdx.x * 256 + threadIdx.x;     // 16384 rows
    const float4* p = reinterpret_cast<const float4*>(g_part + (size_t)r * 32);
    float s = 0.0f;
#pragma unroll
    for (int i = 0; i < 8; i++) {
        float4 v = p[i];
        s += (v.x + v.y) + (v.z + v.w);
    }
    g_sumsq[r] = s;
}

// ---------------------------------------------------------------------------
// Launcher
// ---------------------------------------------------------------------------
extern "C" void kernel_launch(void* const* d_in, const int* in_sizes, int n_in,
                              void* d_out, int out_size) {
    const float* x  = (const float*)d_in[0];
    const float* Wi = (const float*)d_in[1];
    const float* Wf = (const float*)d_in[2];
    const float* Wg = (const float*)d_in[3];
    const float* wn = (const float*)d_in[4];
    const float* Wo = (const float*)d_in[5];
    float* out = (float*)d_out;

    cudaFuncSetAttribute(gemm_f16_kernel<0>,
                         cudaFuncAttributeMaxDynamicSharedMemorySize, SMEM_BYTES);
    cudaFuncSetAttribute(gemm_f16_kernel<1>,
                         cudaFuncAttributeMaxDynamicSharedMemorySize, SMEM_BYTES);

    __half* xh;  cudaGetSymbolAddress((void**)&xh, g_xh);

    // 0) fp32 -> fp16 conversions
    constexpr int WEL = DD * DD;             // 4,194,304
    f2h_x_kernel<<<PLANE / 4096, 256>>>(x, xh);
    f2h_w_kernel<<<dim3(WEL / 4096, 4), 256>>>(Wi, Wf, Wg, Wo);

    // 1) Fused projection GEMM (N = 6144 concat) + gate activations in epilogue
    dim3 g1(3 * DD / NT, RM / MT);   // (48, 128), N fastest
    gemm_f16_kernel<0><<<g1, 256, SMEM_BYTES>>>(nullptr);

    // 2) Pure-FMA chunked linear scan + RMS statistics
    scan_chunk_kernel<<<(BB * NCH * DP) / 256, 256>>>();
    scan_prefix_kernel<<<(BB * DP) / 256, 256>>>();
    scan_apply_kernel<<<(BB * NCH * DP) / 256, 256>>>(wn);
    sumsq_reduce_kernel<<<RM / 256, 256>>>();

    // 3) Output GEMM with fused RMSNorm row scaling
    dim3 g2(DD / NT, RM / MT);       // (16, 128), N fastest
    gemm_f16_kernel<1><<<g2, 256, SMEM_BYTES>>>(out);
}